// round 1
// baseline (speedup 1.0000x reference)
#include <cuda_runtime.h>
#include <math.h>

// Problem constants (fixed by setup_inputs)
#define BATCH  8
#define CH     192
#define C3     576
#define NVOX   13824       // 24*24*24
#define HEADS  6
#define HD     32
#define SLICES 54
#define SLICE_N 256        // SLICES*SLICE_N == NVOX
#define EPSN   1e-12f

// Scratch (device globals: no allocation allowed in kernel_launch)
__device__ float g_qkv[(size_t)BATCH * C3 * NVOX];                 // 254.8 MB
__device__ float g_spart[(size_t)BATCH * HEADS * SLICES * 1088];   // partial S(1024)+nq(32)+nk(32)
__device__ float g_attn[BATCH * HEADS * HD * HD];
__device__ float g_M[BATCH * CH * CH];

// ---------------------------------------------------------------------------
// Kernel 1: qkv = W(576x192) @ X[b](192x13824) + bias   -> g_qkv (B,576,N)
// Tiling: BM=64, BN=128, BK=8, 256 threads, microtile 8x4.
// ---------------------------------------------------------------------------
__global__ __launch_bounds__(256) void qkv_gemm(const float* __restrict__ x,
                                                const float* __restrict__ w,
                                                const float* __restrict__ bias)
{
    __shared__ float As[8][68];    // [k][m], padded (16B-aligned rows, low conflicts)
    __shared__ float Bs[8][128];   // [k][n]

    const int b  = blockIdx.z;
    const int m0 = blockIdx.y * 64;
    const int n0 = blockIdx.x * 128;
    const int t  = threadIdx.x;
    const int tr = t >> 5;         // 0..7  thread row group (8 rows each)
    const int tc = t & 31;         // 0..31 thread col group (4 cols each)

    const float* xb = x + (size_t)b * CH * NVOX;

    float acc[8][4];
#pragma unroll
    for (int i = 0; i < 8; i++)
#pragma unroll
        for (int j = 0; j < 4; j++) acc[i][j] = 0.f;

    const int arow = t >> 2;          // 0..63
    const int acol = (t & 3) * 2;     // 0,2,4,6

    for (int k0 = 0; k0 < CH; k0 += 8) {
        float2 av = *(const float2*)(w + (m0 + arow) * CH + k0 + acol);
        float4 bv = *(const float4*)(xb + (size_t)(k0 + (t >> 5)) * NVOX + n0 + (tc << 2));
        __syncthreads();
        As[acol][arow]     = av.x;
        As[acol + 1][arow] = av.y;
        *(float4*)&Bs[t >> 5][tc << 2] = bv;
        __syncthreads();
#pragma unroll
        for (int k = 0; k < 8; k++) {
            float4 a0 = *(const float4*)&As[k][tr * 8];
            float4 a1 = *(const float4*)&As[k][tr * 8 + 4];
            float4 bb = *(const float4*)&Bs[k][tc * 4];
            float ar[8] = {a0.x, a0.y, a0.z, a0.w, a1.x, a1.y, a1.z, a1.w};
            float br[4] = {bb.x, bb.y, bb.z, bb.w};
#pragma unroll
            for (int i = 0; i < 8; i++)
#pragma unroll
                for (int j = 0; j < 4; j++) acc[i][j] += ar[i] * br[j];
        }
    }

    float* ob = g_qkv + (size_t)b * C3 * NVOX;
#pragma unroll
    for (int i = 0; i < 8; i++) {
        const int m = m0 + tr * 8 + i;
        const float bsv = bias[m];
        float4 r = make_float4(acc[i][0] + bsv, acc[i][1] + bsv,
                               acc[i][2] + bsv, acc[i][3] + bsv);
        *(float4*)(ob + (size_t)m * NVOX + n0 + tc * 4) = r;
    }
}

// ---------------------------------------------------------------------------
// Kernel 2: partial scores per (b,h,slice):
//   Sp[c][d] = sum_n q[c,n]*k[d,n],  plus partial squared norms.
//   q[c,n] = g_qkv[b][n*576 + h*32 + c], k at +192 (faithful torch reshape).
// ---------------------------------------------------------------------------
__global__ __launch_bounds__(256) void scores_kernel()
{
    __shared__ float Qs[32][33];
    __shared__ float Ks[32][33];

    const int slice = blockIdx.x;
    const int h     = blockIdx.y;
    const int b     = blockIdx.z;
    const int t     = threadIdx.x;

    const float* base = g_qkv + (size_t)b * C3 * NVOX;

    const int lc  = t & 31;      // load channel
    const int lnn = t >> 5;      // load n-sub (0..7), +i*8
    const int cc  = t >> 3;      // compute row c (0..31)
    const int d0  = (t & 7) << 2;// compute cols d0..d0+3

    float a0 = 0.f, a1 = 0.f, a2 = 0.f, a3 = 0.f;
    float nrm = 0.f;

    for (int ci = 0; ci < 8; ci++) {
        const int nb = slice * SLICE_N + ci * 32;
        __syncthreads();
#pragma unroll
        for (int i = 0; i < 4; i++) {
            const int nn = lnn + i * 8;
            const size_t row = (size_t)(nb + nn) * C3 + h * HD + lc;
            Qs[lc][nn] = base[row];
            Ks[lc][nn] = base[row + CH];
        }
        __syncthreads();
#pragma unroll
        for (int nn = 0; nn < 32; nn++) {
            const float qv = Qs[cc][nn];
            a0 += qv * Ks[d0 + 0][nn];
            a1 += qv * Ks[d0 + 1][nn];
            a2 += qv * Ks[d0 + 2][nn];
            a3 += qv * Ks[d0 + 3][nn];
        }
        if (t < 32) {
#pragma unroll
            for (int nn = 0; nn < 32; nn++) { float v = Qs[t][nn]; nrm += v * v; }
        } else if (t < 64) {
#pragma unroll
            for (int nn = 0; nn < 32; nn++) { float v = Ks[t - 32][nn]; nrm += v * v; }
        }
    }

    float* sp = g_spart + (size_t)((b * HEADS + h) * SLICES + slice) * 1088;
    sp[cc * 32 + d0 + 0] = a0;
    sp[cc * 32 + d0 + 1] = a1;
    sp[cc * 32 + d0 + 2] = a2;
    sp[cc * 32 + d0 + 3] = a3;
    if (t < 32)       sp[1024 + t] = nrm;
    else if (t < 64)  sp[1056 + (t - 32)] = nrm;
}

// ---------------------------------------------------------------------------
// Kernel 2b: reduce partials (deterministic order), normalize, temperature,
//            row softmax over d -> g_attn (B,heads,32,32)
// ---------------------------------------------------------------------------
__global__ __launch_bounds__(256) void softmax_kernel(const float* __restrict__ temp)
{
    __shared__ float sS[1024];
    __shared__ float nq[32];
    __shared__ float nk[32];

    const int h = blockIdx.x;
    const int b = blockIdx.y;
    const int t = threadIdx.x;

    const float* sp = g_spart + (size_t)((b * HEADS + h) * SLICES) * 1088;

#pragma unroll
    for (int i = 0; i < 4; i++) {
        const int e = t + i * 256;
        float a = 0.f;
        for (int s = 0; s < SLICES; s++) a += sp[s * 1088 + e];
        sS[e] = a;
    }
    if (t < 64) {
        float a = 0.f;
        const int off = 1024 + t;
        for (int s = 0; s < SLICES; s++) a += sp[s * 1088 + off];
        const float r = fmaxf(sqrtf(a), EPSN);
        if (t < 32) nq[t] = r; else nk[t - 32] = r;
    }
    __syncthreads();

    const int w    = t >> 5;
    const int lane = t & 31;
    const float tv = temp[h];
    float* ab = g_attn + (size_t)((b * HEADS + h) * HD) * HD;

    for (int r = 0; r < 4; r++) {
        const int c = w * 4 + r;
        float L = sS[c * 32 + lane] / (nq[c] * nk[lane]) * tv;
        float mx = L;
#pragma unroll
        for (int o = 16; o > 0; o >>= 1) mx = fmaxf(mx, __shfl_xor_sync(0xffffffffu, mx, o));
        const float ev = expf(L - mx);
        float sm = ev;
#pragma unroll
        for (int o = 16; o > 0; o >>= 1) sm += __shfl_xor_sync(0xffffffffu, sm, o);
        ab[c * 32 + lane] = ev / sm;
    }
}

// ---------------------------------------------------------------------------
// Kernel 3a: fold proj_w through attn:
//   M[b][o][h*32+d] = sum_cc proj_w[o, cc*6+h] * attn[b,h,cc,d]
// (accounts for the out.transpose(1,2) channel interleave: channel = cc*heads+h)
// ---------------------------------------------------------------------------
__global__ __launch_bounds__(192) void mmix_kernel(const float* __restrict__ pw)
{
    __shared__ float att[32][33];
    const int h = blockIdx.x;
    const int b = blockIdx.y;
    const int t = threadIdx.x;

    const float* ab = g_attn + (size_t)((b * HEADS + h) * HD) * HD;
    for (int e = t; e < 1024; e += 192) att[e >> 5][e & 31] = ab[e];
    __syncthreads();

    float pwr[32];
#pragma unroll
    for (int cc = 0; cc < 32; cc++) pwr[cc] = pw[t * CH + cc * HEADS + h];

    float* Mb = g_M + (size_t)b * CH * CH + t * CH + h * HD;
#pragma unroll 4
    for (int d = 0; d < 32; d++) {
        float s = 0.f;
#pragma unroll
        for (int cc = 0; cc < 32; cc++) s += pwr[cc] * att[cc][d];
        Mb[d] = s;
    }
}

// ---------------------------------------------------------------------------
// Kernel 3b: y[b] = M[b](192x192) @ V[b](192x13824) + proj_b
//   V[b][j][n] = g_qkv[b][n*576 + 384 + j]  (strided gather, 64B-sector perfect)
// ---------------------------------------------------------------------------
__global__ __launch_bounds__(256) void out_gemm(float* __restrict__ y,
                                                const float* __restrict__ pbias)
{
    __shared__ float As[8][68];
    __shared__ float Bs[8][132];

    const int b  = blockIdx.z;
    const int m0 = blockIdx.y * 64;
    const int n0 = blockIdx.x * 128;
    const int t  = threadIdx.x;
    const int tr = t >> 5;
    const int tc = t & 31;

    const float* Mb = g_M + (size_t)b * CH * CH;
    const float* vb = g_qkv + (size_t)b * C3 * NVOX + 2 * CH;  // +384 (v section)

    float acc[8][4];
#pragma unroll
    for (int i = 0; i < 8; i++)
#pragma unroll
        for (int j = 0; j < 4; j++) acc[i][j] = 0.f;

    const int arow = t >> 2;
    const int acol = (t & 3) * 2;
    const int bn   = t >> 1;          // 0..127
    const int bj   = (t & 1) * 4;     // 0 or 4

    for (int k0 = 0; k0 < CH; k0 += 8) {
        float2 av = *(const float2*)(Mb + (m0 + arow) * CH + k0 + acol);
        float4 bv = *(const float4*)(vb + (size_t)(n0 + bn) * C3 + k0 + bj);
        __syncthreads();
        As[acol][arow]     = av.x;
        As[acol + 1][arow] = av.y;
        Bs[bj + 0][bn] = bv.x;
        Bs[bj + 1][bn] = bv.y;
        Bs[bj + 2][bn] = bv.z;
        Bs[bj + 3][bn] = bv.w;
        __syncthreads();
#pragma unroll
        for (int k = 0; k < 8; k++) {
            float4 a0 = *(const float4*)&As[k][tr * 8];
            float4 a1 = *(const float4*)&As[k][tr * 8 + 4];
            float4 bb = *(const float4*)&Bs[k][tc * 4];
            float ar[8] = {a0.x, a0.y, a0.z, a0.w, a1.x, a1.y, a1.z, a1.w};
            float br[4] = {bb.x, bb.y, bb.z, bb.w};
#pragma unroll
            for (int i = 0; i < 8; i++)
#pragma unroll
                for (int j = 0; j < 4; j++) acc[i][j] += ar[i] * br[j];
        }
    }

#pragma unroll
    for (int i = 0; i < 8; i++) {
        const int m = m0 + tr * 8 + i;
        const float bsv = pbias[m];
        float4 r = make_float4(acc[i][0] + bsv, acc[i][1] + bsv,
                               acc[i][2] + bsv, acc[i][3] + bsv);
        *(float4*)(y + (size_t)b * CH * NVOX + (size_t)m * NVOX + n0 + tc * 4) = r;
    }
}

// ---------------------------------------------------------------------------
extern "C" void kernel_launch(void* const* d_in, const int* in_sizes, int n_in,
                              void* d_out, int out_size)
{
    const float* x      = (const float*)d_in[0];
    const float* qkv_w  = (const float*)d_in[1];
    const float* qkv_b  = (const float*)d_in[2];
    const float* temp   = (const float*)d_in[3];
    const float* proj_w = (const float*)d_in[4];
    const float* proj_b = (const float*)d_in[5];
    float* y = (float*)d_out;

    qkv_gemm   <<<dim3(NVOX / 128, C3 / 64, BATCH), 256>>>(x, qkv_w, qkv_b);
    scores_kernel<<<dim3(SLICES, HEADS, BATCH), 256>>>();
    softmax_kernel<<<dim3(HEADS, BATCH), 256>>>(temp);
    mmix_kernel<<<dim3(HEADS, BATCH), 192>>>(proj_w);
    out_gemm   <<<dim3(NVOX / 128, CH / 64, BATCH), 256>>>(y, proj_b);
}

// round 2
// speedup vs baseline: 1.9492x; 1.9492x over previous
#include <cuda_runtime.h>
#include <math.h>

// Problem constants (fixed by setup_inputs)
#define BATCH  8
#define CH     192
#define C3     576
#define NVOX   13824       // 24*24*24
#define HEADS  6
#define HD     32
#define SLICES 54
#define SLICE_N 256        // SLICES*SLICE_N == NVOX
#define EPSN   1e-12f

// Scratch (device globals: no allocation allowed in kernel_launch)
__device__ float g_qkv[(size_t)BATCH * C3 * NVOX];                 // flat (B, 576, N) buffer
__device__ float g_spart[(size_t)BATCH * HEADS * SLICES * 1088];   // partial S(1024)+nq(32)+nk(32)
__device__ float g_attn[BATCH * HEADS * HD * HD];
__device__ float g_M[BATCH * CH * CH];

// ---------------------------------------------------------------------------
// tf32 helpers
// ---------------------------------------------------------------------------
__device__ __forceinline__ unsigned f2tf(float f) {
    unsigned u;
    asm("cvt.rna.tf32.f32 %0, %1;" : "=r"(u) : "f"(f));
    return u;
}

__device__ __forceinline__ void mma_tf32(float* c, const unsigned* a, const unsigned* b) {
    asm volatile(
        "mma.sync.aligned.m16n8k8.row.col.f32.tf32.tf32.f32 "
        "{%0,%1,%2,%3},{%4,%5,%6,%7},{%8,%9},{%0,%1,%2,%3};"
        : "+f"(c[0]), "+f"(c[1]), "+f"(c[2]), "+f"(c[3])
        : "r"(a[0]), "r"(a[1]), "r"(a[2]), "r"(a[3]), "r"(b[0]), "r"(b[1]));
}

// ---------------------------------------------------------------------------
// Kernel 1 (tensor core): qkv = W(576x192) @ X[b](192x13824) + bias
// BM=64, BN=256, BK=16, 256 thr, warp tile 32x64 (2m x 8n of m16n8k8).
// As[m][20] (m-major), Bs[k][264] (k-major, n contiguous).
// ---------------------------------------------------------------------------
__global__ __launch_bounds__(256, 2) void qkv_gemm_tc(const float* __restrict__ x,
                                                      const float* __restrict__ w,
                                                      const float* __restrict__ bias)
{
    __shared__ unsigned As[64 * 20];
    __shared__ unsigned Bs[16 * 264];

    const int b  = blockIdx.z;
    const int m0 = blockIdx.y * 64;
    const int n0 = blockIdx.x * 256;
    const int t  = threadIdx.x;
    const int wid  = t >> 5;
    const int lane = t & 31;
    const int wm = wid >> 2;          // 0..1
    const int wn = wid & 3;           // 0..3
    const int gid  = lane >> 2;       // 0..7
    const int tid4 = lane & 3;        // 0..3

    const float* xb = x + (size_t)b * CH * NVOX;

    float acc[2][8][4];
#pragma unroll
    for (int i = 0; i < 2; i++)
#pragma unroll
        for (int j = 0; j < 8; j++)
#pragma unroll
            for (int e = 0; e < 4; e++) acc[i][j][e] = 0.f;

    const int arow = t >> 2;          // 0..63
    const int akq  = (t & 3) * 4;     // 0,4,8,12

    for (int k0 = 0; k0 < CH; k0 += 16) {
        // gmem -> regs
        float4 av = *(const float4*)(w + (size_t)(m0 + arow) * CH + k0 + akq);
        float4 bv[4];
#pragma unroll
        for (int i = 0; i < 4; i++) {
            const int idx  = i * 256 + t;
            const int krow = idx >> 6;        // 0..15
            const int nq   = idx & 63;        // 0..63
            bv[i] = *(const float4*)(xb + (size_t)(k0 + krow) * NVOX + n0 + nq * 4);
        }
        __syncthreads();
        // regs -> smem (tf32)
        {
            unsigned* d = &As[arow * 20 + akq];
            d[0] = f2tf(av.x); d[1] = f2tf(av.y); d[2] = f2tf(av.z); d[3] = f2tf(av.w);
        }
#pragma unroll
        for (int i = 0; i < 4; i++) {
            const int idx  = i * 256 + t;
            const int krow = idx >> 6;
            const int nq   = idx & 63;
            unsigned* d = &Bs[krow * 264 + nq * 4];
            d[0] = f2tf(bv[i].x); d[1] = f2tf(bv[i].y); d[2] = f2tf(bv[i].z); d[3] = f2tf(bv[i].w);
        }
        __syncthreads();

#pragma unroll
        for (int kk = 0; kk < 16; kk += 8) {
            unsigned af[2][4], bf[8][2];
#pragma unroll
            for (int mt = 0; mt < 2; mt++) {
                const int row = wm * 32 + mt * 16 + gid;
                af[mt][0] = As[row * 20 + kk + tid4];
                af[mt][1] = As[(row + 8) * 20 + kk + tid4];
                af[mt][2] = As[row * 20 + kk + tid4 + 4];
                af[mt][3] = As[(row + 8) * 20 + kk + tid4 + 4];
            }
#pragma unroll
            for (int nt = 0; nt < 8; nt++) {
                const int col = wn * 64 + nt * 8 + gid;
                bf[nt][0] = Bs[(kk + tid4) * 264 + col];
                bf[nt][1] = Bs[(kk + tid4 + 4) * 264 + col];
            }
#pragma unroll
            for (int mt = 0; mt < 2; mt++)
#pragma unroll
                for (int nt = 0; nt < 8; nt++)
                    mma_tf32(acc[mt][nt], af[mt], bf[nt]);
        }
    }

    float* ob = g_qkv + (size_t)b * C3 * NVOX;
#pragma unroll
    for (int mt = 0; mt < 2; mt++) {
        const int r0 = m0 + wm * 32 + mt * 16 + gid;
        const float b0 = bias[r0];
        const float b1 = bias[r0 + 8];
#pragma unroll
        for (int nt = 0; nt < 8; nt++) {
            const int col = n0 + wn * 64 + nt * 8 + 2 * tid4;
            *(float2*)(ob + (size_t)r0 * NVOX + col) =
                make_float2(acc[mt][nt][0] + b0, acc[mt][nt][1] + b0);
            *(float2*)(ob + (size_t)(r0 + 8) * NVOX + col) =
                make_float2(acc[mt][nt][2] + b1, acc[mt][nt][3] + b1);
        }
    }
}

// ---------------------------------------------------------------------------
// Kernel 2: partial scores per (b,h,slice):
//   Sp[c][d] = sum_n q[c,n]*k[d,n],  plus partial squared norms.
//   q[c,n] = g_qkv[b][n*576 + h*32 + c], k at +192 (faithful torch reshape).
// ---------------------------------------------------------------------------
__global__ __launch_bounds__(256) void scores_kernel()
{
    __shared__ float Qs[32][33];
    __shared__ float Ks[32][33];

    const int slice = blockIdx.x;
    const int h     = blockIdx.y;
    const int b     = blockIdx.z;
    const int t     = threadIdx.x;

    const float* base = g_qkv + (size_t)b * C3 * NVOX;

    const int lc  = t & 31;
    const int lnn = t >> 5;
    const int cc  = t >> 3;
    const int d0  = (t & 7) << 2;

    float a0 = 0.f, a1 = 0.f, a2 = 0.f, a3 = 0.f;
    float nrm = 0.f;

    for (int ci = 0; ci < 8; ci++) {
        const int nb = slice * SLICE_N + ci * 32;
        __syncthreads();
#pragma unroll
        for (int i = 0; i < 4; i++) {
            const int nn = lnn + i * 8;
            const size_t row = (size_t)(nb + nn) * C3 + h * HD + lc;
            Qs[lc][nn] = base[row];
            Ks[lc][nn] = base[row + CH];
        }
        __syncthreads();
#pragma unroll
        for (int nn = 0; nn < 32; nn++) {
            const float qv = Qs[cc][nn];
            a0 += qv * Ks[d0 + 0][nn];
            a1 += qv * Ks[d0 + 1][nn];
            a2 += qv * Ks[d0 + 2][nn];
            a3 += qv * Ks[d0 + 3][nn];
        }
        if (t < 32) {
#pragma unroll
            for (int nn = 0; nn < 32; nn++) { float v = Qs[t][nn]; nrm += v * v; }
        } else if (t < 64) {
#pragma unroll
            for (int nn = 0; nn < 32; nn++) { float v = Ks[t - 32][nn]; nrm += v * v; }
        }
    }

    float* sp = g_spart + (size_t)((b * HEADS + h) * SLICES + slice) * 1088;
    sp[cc * 32 + d0 + 0] = a0;
    sp[cc * 32 + d0 + 1] = a1;
    sp[cc * 32 + d0 + 2] = a2;
    sp[cc * 32 + d0 + 3] = a3;
    if (t < 32)       sp[1024 + t] = nrm;
    else if (t < 64)  sp[1056 + (t - 32)] = nrm;
}

// ---------------------------------------------------------------------------
// Kernel 2b: reduce partials, normalize, temperature, row softmax -> g_attn
// ---------------------------------------------------------------------------
__global__ __launch_bounds__(256) void softmax_kernel(const float* __restrict__ temp)
{
    __shared__ float sS[1024];
    __shared__ float nq[32];
    __shared__ float nk[32];

    const int h = blockIdx.x;
    const int b = blockIdx.y;
    const int t = threadIdx.x;

    const float* sp = g_spart + (size_t)((b * HEADS + h) * SLICES) * 1088;

#pragma unroll
    for (int i = 0; i < 4; i++) {
        const int e = t + i * 256;
        float a = 0.f;
        for (int s = 0; s < SLICES; s++) a += sp[s * 1088 + e];
        sS[e] = a;
    }
    if (t < 64) {
        float a = 0.f;
        const int off = 1024 + t;
        for (int s = 0; s < SLICES; s++) a += sp[s * 1088 + off];
        const float r = fmaxf(sqrtf(a), EPSN);
        if (t < 32) nq[t] = r; else nk[t - 32] = r;
    }
    __syncthreads();

    const int w    = t >> 5;
    const int lane = t & 31;
    const float tv = temp[h];
    float* ab = g_attn + (size_t)((b * HEADS + h) * HD) * HD;

    for (int r = 0; r < 4; r++) {
        const int c = w * 4 + r;
        float L = sS[c * 32 + lane] / (nq[c] * nk[lane]) * tv;
        float mx = L;
#pragma unroll
        for (int o = 16; o > 0; o >>= 1) mx = fmaxf(mx, __shfl_xor_sync(0xffffffffu, mx, o));
        const float ev = expf(L - mx);
        float sm = ev;
#pragma unroll
        for (int o = 16; o > 0; o >>= 1) sm += __shfl_xor_sync(0xffffffffu, sm, o);
        ab[c * 32 + lane] = ev / sm;
    }
}

// ---------------------------------------------------------------------------
// Kernel 3a: fold proj_w through attn:
//   M[b][o][h*32+d] = sum_cc proj_w[o, cc*6+h] * attn[b,h,cc,d]
// ---------------------------------------------------------------------------
__global__ __launch_bounds__(192) void mmix_kernel(const float* __restrict__ pw)
{
    __shared__ float att[32][33];
    const int h = blockIdx.x;
    const int b = blockIdx.y;
    const int t = threadIdx.x;

    const float* ab = g_attn + (size_t)((b * HEADS + h) * HD) * HD;
    for (int e = t; e < 1024; e += 192) att[e >> 5][e & 31] = ab[e];
    __syncthreads();

    float pwr[32];
#pragma unroll
    for (int cc = 0; cc < 32; cc++) pwr[cc] = pw[t * CH + cc * HEADS + h];

    float* Mb = g_M + (size_t)b * CH * CH + t * CH + h * HD;
#pragma unroll 4
    for (int d = 0; d < 32; d++) {
        float s = 0.f;
#pragma unroll
        for (int cc = 0; cc < 32; cc++) s += pwr[cc] * att[cc][d];
        Mb[d] = s;
    }
}

// ---------------------------------------------------------------------------
// Kernel 3b (tensor core): y[b] = M[b](192x192) @ V[b](192x13824) + proj_b
//   V[b][k][n] = g_qkv[b][n*576 + 384 + k]  (strided gather, sector-perfect)
// As[m][20] (m-major), Bs[n][20] (n-major, k contiguous).
// ---------------------------------------------------------------------------
__global__ __launch_bounds__(256, 2) void out_gemm_tc(float* __restrict__ y,
                                                      const float* __restrict__ pbias)
{
    __shared__ unsigned As[64 * 20];
    __shared__ unsigned Bs[256 * 20];

    const int b  = blockIdx.z;
    const int m0 = blockIdx.y * 64;
    const int n0 = blockIdx.x * 256;
    const int t  = threadIdx.x;
    const int wid  = t >> 5;
    const int lane = t & 31;
    const int wm = wid >> 2;
    const int wn = wid & 3;
    const int gid  = lane >> 2;
    const int tid4 = lane & 3;

    const float* Mb = g_M + (size_t)b * CH * CH;
    const float* vb = g_qkv + (size_t)b * C3 * NVOX + 2 * CH;   // +384 (v section)

    float acc[2][8][4];
#pragma unroll
    for (int i = 0; i < 2; i++)
#pragma unroll
        for (int j = 0; j < 8; j++)
#pragma unroll
            for (int e = 0; e < 4; e++) acc[i][j][e] = 0.f;

    const int arow = t >> 2;
    const int akq  = (t & 3) * 4;

    for (int k0 = 0; k0 < CH; k0 += 16) {
        float4 av = *(const float4*)(Mb + (size_t)(m0 + arow) * CH + k0 + akq);
        float4 bv[4];
#pragma unroll
        for (int i = 0; i < 4; i++) {
            const int idx = i * 256 + t;
            const int n   = idx >> 2;         // 0..255
            const int kq  = (idx & 3) * 4;    // 0,4,8,12
            bv[i] = *(const float4*)(vb + (size_t)(n0 + n) * C3 + k0 + kq);
        }
        __syncthreads();
        {
            unsigned* d = &As[arow * 20 + akq];
            d[0] = f2tf(av.x); d[1] = f2tf(av.y); d[2] = f2tf(av.z); d[3] = f2tf(av.w);
        }
#pragma unroll
        for (int i = 0; i < 4; i++) {
            const int idx = i * 256 + t;
            const int n   = idx >> 2;
            const int kq  = (idx & 3) * 4;
            unsigned* d = &Bs[n * 20 + kq];
            d[0] = f2tf(bv[i].x); d[1] = f2tf(bv[i].y); d[2] = f2tf(bv[i].z); d[3] = f2tf(bv[i].w);
        }
        __syncthreads();

#pragma unroll
        for (int kk = 0; kk < 16; kk += 8) {
            unsigned af[2][4], bf[8][2];
#pragma unroll
            for (int mt = 0; mt < 2; mt++) {
                const int row = wm * 32 + mt * 16 + gid;
                af[mt][0] = As[row * 20 + kk + tid4];
                af[mt][1] = As[(row + 8) * 20 + kk + tid4];
                af[mt][2] = As[row * 20 + kk + tid4 + 4];
                af[mt][3] = As[(row + 8) * 20 + kk + tid4 + 4];
            }
#pragma unroll
            for (int nt = 0; nt < 8; nt++) {
                const int col = wn * 64 + nt * 8 + gid;
                bf[nt][0] = Bs[col * 20 + kk + tid4];
                bf[nt][1] = Bs[col * 20 + kk + tid4 + 4];
            }
#pragma unroll
            for (int mt = 0; mt < 2; mt++)
#pragma unroll
                for (int nt = 0; nt < 8; nt++)
                    mma_tf32(acc[mt][nt], af[mt], bf[nt]);
        }
    }

    float* yb = y + (size_t)b * CH * NVOX;
#pragma unroll
    for (int mt = 0; mt < 2; mt++) {
        const int r0 = m0 + wm * 32 + mt * 16 + gid;
        const float b0 = pbias[r0];
        const float b1 = pbias[r0 + 8];
#pragma unroll
        for (int nt = 0; nt < 8; nt++) {
            const int col = n0 + wn * 64 + nt * 8 + 2 * tid4;
            *(float2*)(yb + (size_t)r0 * NVOX + col) =
                make_float2(acc[mt][nt][0] + b0, acc[mt][nt][1] + b0);
            *(float2*)(yb + (size_t)(r0 + 8) * NVOX + col) =
                make_float2(acc[mt][nt][2] + b1, acc[mt][nt][3] + b1);
        }
    }
}

// ---------------------------------------------------------------------------
extern "C" void kernel_launch(void* const* d_in, const int* in_sizes, int n_in,
                              void* d_out, int out_size)
{
    const float* x      = (const float*)d_in[0];
    const float* qkv_w  = (const float*)d_in[1];
    const float* qkv_b  = (const float*)d_in[2];
    const float* temp   = (const float*)d_in[3];
    const float* proj_w = (const float*)d_in[4];
    const float* proj_b = (const float*)d_in[5];
    float* y = (float*)d_out;

    qkv_gemm_tc  <<<dim3(NVOX / 256, C3 / 64, BATCH), 256>>>(x, qkv_w, qkv_b);
    scores_kernel<<<dim3(SLICES, HEADS, BATCH), 256>>>();
    softmax_kernel<<<dim3(HEADS, BATCH), 256>>>(temp);
    mmix_kernel  <<<dim3(HEADS, BATCH), 192>>>(proj_w);
    out_gemm_tc  <<<dim3(NVOX / 256, CH / 64, BATCH), 256>>>(y, proj_b);
}

// round 3
// speedup vs baseline: 2.2034x; 1.1304x over previous
#include <cuda_runtime.h>
#include <math.h>

#define BATCH  8
#define CH     192
#define C3     576
#define NVOX   13824       // 24*24*24
#define HEADS  6
#define HD     32
#define EPSN   1e-12f

// Scratch
__device__ float g_Z[(size_t)BATCH * CH * NVOX];     // Z = Gw @ X   (85 MB)
__device__ float g_V[(size_t)BATCH * NVOX * CH];     // Vbuf[n][k]   (85 MB)
__device__ float g_Gw[CH * CH];
__device__ float g_wb[CH];
__device__ float g_c[4];                             // [0] = b2
__device__ float g_spart[BATCH * HEADS * 6 * 1152];  // S1(1024)+d1q+d1k+wbq+wbk
__device__ float g_attn[BATCH * HEADS * HD * HD];
__device__ float g_M[BATCH * CH * CH];

// ---------------------------------------------------------------------------
__device__ __forceinline__ unsigned f2tf(float f) {
    unsigned u;
    asm("cvt.rna.tf32.f32 %0, %1;" : "=r"(u) : "f"(f));
    return u;
}
__device__ __forceinline__ void mma_tf32(float* c, const unsigned* a, const unsigned* b) {
    asm volatile(
        "mma.sync.aligned.m16n8k8.row.col.f32.tf32.tf32.f32 "
        "{%0,%1,%2,%3},{%4,%5,%6,%7},{%8,%9},{%0,%1,%2,%3};"
        : "+f"(c[0]), "+f"(c[1]), "+f"(c[2]), "+f"(c[3])
        : "r"(a[0]), "r"(a[1]), "r"(a[2]), "r"(a[3]), "r"(b[0]), "r"(b[1]));
}

// ---------------------------------------------------------------------------
// K0a: Gw = W^T W  (192x192, fp32). grid(6,6), 256 thr.
// ---------------------------------------------------------------------------
__global__ __launch_bounds__(256) void gw_kernel(const float* __restrict__ w)
{
    __shared__ float Wi[32][33];
    __shared__ float Wj[32][33];
    const int i0 = blockIdx.x * 32, j0 = blockIdx.y * 32;
    const int t = threadIdx.x;
    const int ti = t & 31, tj = (t >> 5) * 4;
    float acc[4] = {0.f, 0.f, 0.f, 0.f};

    for (int a0 = 0; a0 < C3; a0 += 32) {
        __syncthreads();
#pragma unroll
        for (int l = 0; l < 4; l++) {
            const int a = (t >> 5) + 8 * l, c = t & 31;
            Wi[a][c] = w[(a0 + a) * CH + i0 + c];
            Wj[a][c] = w[(a0 + a) * CH + j0 + c];
        }
        __syncthreads();
#pragma unroll
        for (int a = 0; a < 32; a++) {
            const float wi = Wi[a][ti];
#pragma unroll
            for (int r = 0; r < 4; r++) acc[r] += wi * Wj[a][tj + r];
        }
    }
#pragma unroll
    for (int r = 0; r < 4; r++) g_Gw[(i0 + ti) * CH + j0 + tj + r] = acc[r];
}

// K0b: wb = W^T beta; b2 = sum beta^2. One block, 256 thr.
__global__ __launch_bounds__(256) void wb_kernel(const float* __restrict__ w,
                                                 const float* __restrict__ beta)
{
    __shared__ float red[64];
    const int t = threadIdx.x;
    if (t < CH) {
        float s = 0.f;
        for (int a = 0; a < C3; a++) s += beta[a] * w[a * CH + t];
        g_wb[t] = s;
    }
    if (t < 64) {
        float p = 0.f;
        for (int a = t; a < C3; a += 64) p += beta[a] * beta[a];
        red[t] = p;
    }
    __syncthreads();
    if (t == 0) {
        float s = 0.f;
        for (int i = 0; i < 64; i++) s += red[i];
        g_c[0] = s;
    }
}

// ---------------------------------------------------------------------------
// K1: Z[b] = Gw(192x192) @ X[b](192x13824).  BM=192, BN=128, BK=16.
// 8 warps = 4m x 2n, warp tile 48x64 (3x8 m16n8k8).
// ---------------------------------------------------------------------------
__global__ __launch_bounds__(256, 1) void z_gemm(const float* __restrict__ x)
{
    __shared__ unsigned As[192 * 20];
    __shared__ unsigned Bs[16 * 136];

    const int b  = blockIdx.z;
    const int n0 = blockIdx.x * 128;
    const int t  = threadIdx.x;
    const int wid = t >> 5, lane = t & 31;
    const int wm = wid >> 1, wn = wid & 1;
    const int gid = lane >> 2, tid4 = lane & 3;

    const float* xb = x + (size_t)b * CH * NVOX;
    float* zb = g_Z + (size_t)b * CH * NVOX;

    float acc[3][8][4];
#pragma unroll
    for (int i = 0; i < 3; i++)
#pragma unroll
        for (int j = 0; j < 8; j++)
#pragma unroll
            for (int e = 0; e < 4; e++) acc[i][j][e] = 0.f;

    float4 ar[3], br[2];
#pragma unroll
    for (int l = 0; l < 3; l++) {
        const int idx = l * 256 + t;
        ar[l] = *(const float4*)(g_Gw + (idx >> 2) * CH + (idx & 3) * 4);
    }
#pragma unroll
    for (int l = 0; l < 2; l++) {
        const int idx = l * 256 + t;
        br[l] = *(const float4*)(xb + (size_t)(idx >> 5) * NVOX + n0 + (idx & 31) * 4);
    }

    for (int k0 = 0; k0 < CH; k0 += 16) {
        __syncthreads();
#pragma unroll
        for (int l = 0; l < 3; l++) {
            const int idx = l * 256 + t;
            unsigned* d = &As[(idx >> 2) * 20 + (idx & 3) * 4];
            d[0] = f2tf(ar[l].x); d[1] = f2tf(ar[l].y); d[2] = f2tf(ar[l].z); d[3] = f2tf(ar[l].w);
        }
#pragma unroll
        for (int l = 0; l < 2; l++) {
            const int idx = l * 256 + t;
            unsigned* d = &Bs[(idx >> 5) * 136 + (idx & 31) * 4];
            d[0] = f2tf(br[l].x); d[1] = f2tf(br[l].y); d[2] = f2tf(br[l].z); d[3] = f2tf(br[l].w);
        }
        __syncthreads();
        if (k0 + 16 < CH) {
#pragma unroll
            for (int l = 0; l < 3; l++) {
                const int idx = l * 256 + t;
                ar[l] = *(const float4*)(g_Gw + (idx >> 2) * CH + k0 + 16 + (idx & 3) * 4);
            }
#pragma unroll
            for (int l = 0; l < 2; l++) {
                const int idx = l * 256 + t;
                br[l] = *(const float4*)(xb + (size_t)(k0 + 16 + (idx >> 5)) * NVOX + n0 + (idx & 31) * 4);
            }
        }
#pragma unroll
        for (int kk = 0; kk < 16; kk += 8) {
            unsigned af[3][4], bf[8][2];
#pragma unroll
            for (int mt = 0; mt < 3; mt++) {
                const int row = wm * 48 + mt * 16 + gid;
                af[mt][0] = As[row * 20 + kk + tid4];
                af[mt][1] = As[(row + 8) * 20 + kk + tid4];
                af[mt][2] = As[row * 20 + kk + tid4 + 4];
                af[mt][3] = As[(row + 8) * 20 + kk + tid4 + 4];
            }
#pragma unroll
            for (int nt = 0; nt < 8; nt++) {
                const int col = wn * 64 + nt * 8 + gid;
                bf[nt][0] = Bs[(kk + tid4) * 136 + col];
                bf[nt][1] = Bs[(kk + tid4 + 4) * 136 + col];
            }
#pragma unroll
            for (int mt = 0; mt < 3; mt++)
#pragma unroll
                for (int nt = 0; nt < 8; nt++)
                    mma_tf32(acc[mt][nt], af[mt], bf[nt]);
        }
    }

#pragma unroll
    for (int mt = 0; mt < 3; mt++) {
        const int r0 = wm * 48 + mt * 16 + gid;
#pragma unroll
        for (int nt = 0; nt < 8; nt++) {
            const int col = n0 + wn * 64 + nt * 8 + 2 * tid4;
            *(float2*)(zb + (size_t)r0 * NVOX + col) = make_float2(acc[mt][nt][0], acc[mt][nt][1]);
            *(float2*)(zb + (size_t)(r0 + 8) * NVOX + col) = make_float2(acc[mt][nt][2], acc[mt][nt][3]);
        }
    }
}

// ---------------------------------------------------------------------------
// K2: Vbuf[b][n*192+j] = W_a . X[:, 576e+384+j] + beta_a,  n = 24a+e.
// Output addressed as [a][p], p = e*192+j (== n*192+j). BM=192(a), BN=96(p).
// 8 warps = 4m x 2n, warp tile 48x48 (3x6 tiles).
// ---------------------------------------------------------------------------
__global__ __launch_bounds__(256, 1) void v_gemm(const float* __restrict__ x,
                                                 const float* __restrict__ w,
                                                 const float* __restrict__ beta)
{
    __shared__ unsigned As[192 * 20];
    __shared__ unsigned Bs[16 * 104];

    const int b  = blockIdx.z;
    const int m0 = blockIdx.y * 192;
    const int p0 = blockIdx.x * 96;
    const int e  = p0 / 192;
    const int j0 = p0 % 192;
    const int t  = threadIdx.x;
    const int wid = t >> 5, lane = t & 31;
    const int wm = wid >> 1, wn = wid & 1;
    const int gid = lane >> 2, tid4 = lane & 3;

    const float* xb = x + (size_t)b * CH * NVOX + 576 * e + 384 + j0;
    float* vb = g_V + (size_t)b * NVOX * CH;

    float acc[3][6][4];
#pragma unroll
    for (int i = 0; i < 3; i++)
#pragma unroll
        for (int j = 0; j < 6; j++)
#pragma unroll
            for (int q = 0; q < 4; q++) acc[i][j][q] = 0.f;

    float4 ar[3], br;
    bool bact = t < 128;
#pragma unroll
    for (int l = 0; l < 3; l++) {
        const int idx = l * 256 + t;
        ar[l] = *(const float4*)(w + (size_t)(m0 + (idx >> 2)) * CH + (idx & 3) * 4);
    }
    float4 br2[2];
#pragma unroll
    for (int l = 0; l < 2; l++) {
        const int idx = l * 256 + t;
        if (idx < 384)
            br2[l] = *(const float4*)(xb + (size_t)(idx / 24) * NVOX + (idx % 24) * 4);
    }
    (void)br; (void)bact;

    for (int k0 = 0; k0 < CH; k0 += 16) {
        __syncthreads();
#pragma unroll
        for (int l = 0; l < 3; l++) {
            const int idx = l * 256 + t;
            unsigned* d = &As[(idx >> 2) * 20 + (idx & 3) * 4];
            d[0] = f2tf(ar[l].x); d[1] = f2tf(ar[l].y); d[2] = f2tf(ar[l].z); d[3] = f2tf(ar[l].w);
        }
#pragma unroll
        for (int l = 0; l < 2; l++) {
            const int idx = l * 256 + t;
            if (idx < 384) {
                unsigned* d = &Bs[(idx / 24) * 104 + (idx % 24) * 4];
                d[0] = f2tf(br2[l].x); d[1] = f2tf(br2[l].y); d[2] = f2tf(br2[l].z); d[3] = f2tf(br2[l].w);
            }
        }
        __syncthreads();
        if (k0 + 16 < CH) {
#pragma unroll
            for (int l = 0; l < 3; l++) {
                const int idx = l * 256 + t;
                ar[l] = *(const float4*)(w + (size_t)(m0 + (idx >> 2)) * CH + k0 + 16 + (idx & 3) * 4);
            }
#pragma unroll
            for (int l = 0; l < 2; l++) {
                const int idx = l * 256 + t;
                if (idx < 384)
                    br2[l] = *(const float4*)(xb + (size_t)(k0 + 16 + idx / 24) * NVOX + (idx % 24) * 4);
            }
        }
#pragma unroll
        for (int kk = 0; kk < 16; kk += 8) {
            unsigned af[3][4], bf[6][2];
#pragma unroll
            for (int mt = 0; mt < 3; mt++) {
                const int row = wm * 48 + mt * 16 + gid;
                af[mt][0] = As[row * 20 + kk + tid4];
                af[mt][1] = As[(row + 8) * 20 + kk + tid4];
                af[mt][2] = As[row * 20 + kk + tid4 + 4];
                af[mt][3] = As[(row + 8) * 20 + kk + tid4 + 4];
            }
#pragma unroll
            for (int nt = 0; nt < 6; nt++) {
                const int col = wn * 48 + nt * 8 + gid;
                bf[nt][0] = Bs[(kk + tid4) * 104 + col];
                bf[nt][1] = Bs[(kk + tid4 + 4) * 104 + col];
            }
#pragma unroll
            for (int mt = 0; mt < 3; mt++)
#pragma unroll
                for (int nt = 0; nt < 6; nt++)
                    mma_tf32(acc[mt][nt], af[mt], bf[nt]);
        }
    }

#pragma unroll
    for (int mt = 0; mt < 3; mt++) {
        const int r0 = m0 + wm * 48 + mt * 16 + gid;   // global a
        const float b0 = beta[r0], b1 = beta[r0 + 8];
#pragma unroll
        for (int nt = 0; nt < 6; nt++) {
            const int pc = p0 + wn * 48 + nt * 8 + 2 * tid4;
            *(float2*)(vb + (size_t)r0 * 4608 + pc) =
                make_float2(acc[mt][nt][0] + b0, acc[mt][nt][1] + b0);
            *(float2*)(vb + (size_t)(r0 + 8) * 4608 + pc) =
                make_float2(acc[mt][nt][2] + b1, acc[mt][nt][3] + b1);
        }
    }
}

// ---------------------------------------------------------------------------
// K3: score partials. grid (islice=6, h=6, b=8), 256 thr.
//   S1[c][d] += sum_{i in slice, e} X[i,uq(c)] * Z[i,uk(d)]
//   plus diag(Xq.Zq), diag(Xk.Zk), wb-dots.
// ---------------------------------------------------------------------------
__global__ __launch_bounds__(256) void scores_kernel(const float* __restrict__ x)
{
    __shared__ float Xq[2][32][36], Zq[2][32][36], Xk[2][32][36], Zk[2][32][36];
    __shared__ float wbs[32];

    const int isl = blockIdx.x, h = blockIdx.y, b = blockIdx.z;
    const int i0  = isl * 32;
    const int t   = threadIdx.x;
    const int h32 = h * 32;

    const float* xb = x + (size_t)b * CH * NVOX;
    const float* zb = g_Z + (size_t)b * CH * NVOX;

    if (t < 32) wbs[t] = g_wb[i0 + t];

    const int li = (t >> 5);     // 0..7 (+8l)
    const int lc = t & 31;
    const int cc = t >> 3;
    const int d0 = (t & 7) << 2;

    float s[4] = {0.f, 0.f, 0.f, 0.f};
    float dac = 0.f, wac = 0.f;

    float rq[4], rzq[4], rk[4], rzk[4];
#pragma unroll
    for (int l = 0; l < 4; l++) {
        const size_t row = (size_t)(i0 + li + 8 * l) * NVOX;
        const int u = h32 + lc;
        rq[l]  = xb[row + u];       rzq[l] = zb[row + u];
        rk[l]  = xb[row + u + 192]; rzk[l] = zb[row + u + 192];
    }
#pragma unroll
    for (int l = 0; l < 4; l++) {
        const int i = li + 8 * l;
        Xq[0][i][lc] = rq[l];  Zq[0][i][lc] = rzq[l];
        Xk[0][i][lc] = rk[l];  Zk[0][i][lc] = rzk[l];
    }
    __syncthreads();

    for (int e = 0; e < 24; e++) {
        const int cur = e & 1, nxt = cur ^ 1;
        if (e < 23) {
            const int u = 576 * (e + 1) + h32 + lc;
#pragma unroll
            for (int l = 0; l < 4; l++) {
                const size_t row = (size_t)(i0 + li + 8 * l) * NVOX;
                rq[l]  = xb[row + u];       rzq[l] = zb[row + u];
                rk[l]  = xb[row + u + 192]; rzk[l] = zb[row + u + 192];
            }
        }
        // compute
#pragma unroll
        for (int i = 0; i < 32; i++) {
            const float qv = Xq[cur][i][cc];
            const float4 zv = *(const float4*)&Zk[cur][i][d0];
            s[0] += qv * zv.x; s[1] += qv * zv.y; s[2] += qv * zv.z; s[3] += qv * zv.w;
        }
        if (t < 32) {
#pragma unroll
            for (int i = 0; i < 32; i++) {
                const float xv = Xq[cur][i][t];
                dac += xv * Zq[cur][i][t];
                wac += wbs[i] * xv;
            }
        } else if (t < 64) {
            const int c = t - 32;
#pragma unroll
            for (int i = 0; i < 32; i++) {
                const float xv = Xk[cur][i][c];
                dac += xv * Zk[cur][i][c];
                wac += wbs[i] * xv;
            }
        }
        if (e < 23) {
#pragma unroll
            for (int l = 0; l < 4; l++) {
                const int i = li + 8 * l;
                Xq[nxt][i][lc] = rq[l];  Zq[nxt][i][lc] = rzq[l];
                Xk[nxt][i][lc] = rk[l];  Zk[nxt][i][lc] = rzk[l];
            }
        }
        __syncthreads();
    }

    float* sp = g_spart + (size_t)((b * HEADS + h) * 6 + isl) * 1152;
    sp[cc * 32 + d0 + 0] = s[0];
    sp[cc * 32 + d0 + 1] = s[1];
    sp[cc * 32 + d0 + 2] = s[2];
    sp[cc * 32 + d0 + 3] = s[3];
    if (t < 32)       { sp[1024 + t] = dac; sp[1088 + t] = wac; }
    else if (t < 64)  { sp[1056 + (t - 32)] = dac; sp[1120 + (t - 32)] = wac; }
}

// ---------------------------------------------------------------------------
// K4: reduce partials, assemble S + bias terms, normalize, softmax -> attn
// ---------------------------------------------------------------------------
__global__ __launch_bounds__(256) void softmax_kernel(const float* __restrict__ temp)
{
    __shared__ float sS[1024];
    __shared__ float snq[32], snk[32], swq[32], swk[32];

    const int h = blockIdx.x, b = blockIdx.y;
    const int t = threadIdx.x;
    const float b2 = g_c[0];
    const float* sp = g_spart + (size_t)((b * HEADS + h) * 6) * 1152;

#pragma unroll
    for (int i = 0; i < 4; i++) {
        const int e = t + i * 256;
        float a = 0.f;
        for (int s = 0; s < 6; s++) a += sp[s * 1152 + e];
        sS[e] = a;
    }
    if (t < 64) {
        float d = 0.f, wv = 0.f;
        const int od = 1024 + t, ow = 1088 + t;
        for (int s = 0; s < 6; s++) { d += sp[s * 1152 + od]; wv += sp[s * 1152 + ow]; }
        const float n2 = d + 2.f * wv + 24.f * b2;
        const float r = fmaxf(sqrtf(fmaxf(n2, 0.f)), EPSN);
        if (t < 32) { snq[t] = r; swq[t] = wv; }
        else        { snk[t - 32] = r; swk[t - 32] = wv; }
    }
    __syncthreads();

    const int w = t >> 5, lane = t & 31;
    const float tv = temp[h];
    float* ab = g_attn + (size_t)((b * HEADS + h) * HD) * HD;

    for (int r = 0; r < 4; r++) {
        const int c = w * 4 + r;
        const float Sfull = sS[c * 32 + lane] + swq[c] + swk[lane] + 24.f * b2;
        float L = Sfull / (snq[c] * snk[lane]) * tv;
        float mx = L;
#pragma unroll
        for (int o = 16; o > 0; o >>= 1) mx = fmaxf(mx, __shfl_xor_sync(0xffffffffu, mx, o));
        const float ev = expf(L - mx);
        float sm = ev;
#pragma unroll
        for (int o = 16; o > 0; o >>= 1) sm += __shfl_xor_sync(0xffffffffu, sm, o);
        ab[c * 32 + lane] = ev / sm;
    }
}

// ---------------------------------------------------------------------------
// K5: M[b][o][h*32+d] = sum_cc proj_w[o, cc*6+h] * attn[b,h,cc,d]
// ---------------------------------------------------------------------------
__global__ __launch_bounds__(192) void mmix_kernel(const float* __restrict__ pw)
{
    __shared__ float att[32][33];
    const int h = blockIdx.x, b = blockIdx.y;
    const int t = threadIdx.x;

    const float* ab = g_attn + (size_t)((b * HEADS + h) * HD) * HD;
    for (int e = t; e < 1024; e += 192) att[e >> 5][e & 31] = ab[e];
    __syncthreads();

    float pwr[32];
#pragma unroll
    for (int cc = 0; cc < 32; cc++) pwr[cc] = pw[t * CH + cc * HEADS + h];

    float* Mb = g_M + (size_t)b * CH * CH + t * CH + h * HD;
#pragma unroll 4
    for (int d = 0; d < 32; d++) {
        float s = 0.f;
#pragma unroll
        for (int cc = 0; cc < 32; cc++) s += pwr[cc] * att[cc][d];
        Mb[d] = s;
    }
}

// ---------------------------------------------------------------------------
// K6: y[b] = M[b](192x192) @ Vbuf[b]^T + proj_b.  Vbuf rows: [n][192].
// BM=192, BN=128. 8 warps 4m x 2n, warp 48x64.
// ---------------------------------------------------------------------------
__global__ __launch_bounds__(256, 1) void out_gemm(float* __restrict__ y,
                                                   const float* __restrict__ pbias)
{
    __shared__ unsigned As[192 * 20];
    __shared__ unsigned Bs[128 * 20];

    const int b  = blockIdx.z;
    const int n0 = blockIdx.x * 128;
    const int t  = threadIdx.x;
    const int wid = t >> 5, lane = t & 31;
    const int wm = wid >> 1, wn = wid & 1;
    const int gid = lane >> 2, tid4 = lane & 3;

    const float* Mb = g_M + (size_t)b * CH * CH;
    const float* vb = g_V + (size_t)b * NVOX * CH;
    float* yb = y + (size_t)b * CH * NVOX;

    float acc[3][8][4];
#pragma unroll
    for (int i = 0; i < 3; i++)
#pragma unroll
        for (int j = 0; j < 8; j++)
#pragma unroll
            for (int e = 0; e < 4; e++) acc[i][j][e] = 0.f;

    float4 ar[3], br[2];
#pragma unroll
    for (int l = 0; l < 3; l++) {
        const int idx = l * 256 + t;
        ar[l] = *(const float4*)(Mb + (idx >> 2) * CH + (idx & 3) * 4);
    }
#pragma unroll
    for (int l = 0; l < 2; l++) {
        const int idx = l * 256 + t;
        br[l] = *(const float4*)(vb + (size_t)(n0 + (idx >> 2)) * CH + (idx & 3) * 4);
    }

    for (int k0 = 0; k0 < CH; k0 += 16) {
        __syncthreads();
#pragma unroll
        for (int l = 0; l < 3; l++) {
            const int idx = l * 256 + t;
            unsigned* d = &As[(idx >> 2) * 20 + (idx & 3) * 4];
            d[0] = f2tf(ar[l].x); d[1] = f2tf(ar[l].y); d[2] = f2tf(ar[l].z); d[3] = f2tf(ar[l].w);
        }
#pragma unroll
        for (int l = 0; l < 2; l++) {
            const int idx = l * 256 + t;
            unsigned* d = &Bs[(idx >> 2) * 20 + (idx & 3) * 4];
            d[0] = f2tf(br[l].x); d[1] = f2tf(br[l].y); d[2] = f2tf(br[l].z); d[3] = f2tf(br[l].w);
        }
        __syncthreads();
        if (k0 + 16 < CH) {
#pragma unroll
            for (int l = 0; l < 3; l++) {
                const int idx = l * 256 + t;
                ar[l] = *(const float4*)(Mb + (idx >> 2) * CH + k0 + 16 + (idx & 3) * 4);
            }
#pragma unroll
            for (int l = 0; l < 2; l++) {
                const int idx = l * 256 + t;
                br[l] = *(const float4*)(vb + (size_t)(n0 + (idx >> 2)) * CH + k0 + 16 + (idx & 3) * 4);
            }
        }
#pragma unroll
        for (int kk = 0; kk < 16; kk += 8) {
            unsigned af[3][4], bf[8][2];
#pragma unroll
            for (int mt = 0; mt < 3; mt++) {
                const int row = wm * 48 + mt * 16 + gid;
                af[mt][0] = As[row * 20 + kk + tid4];
                af[mt][1] = As[(row + 8) * 20 + kk + tid4];
                af[mt][2] = As[row * 20 + kk + tid4 + 4];
                af[mt][3] = As[(row + 8) * 20 + kk + tid4 + 4];
            }
#pragma unroll
            for (int nt = 0; nt < 8; nt++) {
                const int col = wn * 64 + nt * 8 + gid;
                bf[nt][0] = Bs[col * 20 + kk + tid4];
                bf[nt][1] = Bs[col * 20 + kk + tid4 + 4];
            }
#pragma unroll
            for (int mt = 0; mt < 3; mt++)
#pragma unroll
                for (int nt = 0; nt < 8; nt++)
                    mma_tf32(acc[mt][nt], af[mt], bf[nt]);
        }
    }

#pragma unroll
    for (int mt = 0; mt < 3; mt++) {
        const int r0 = wm * 48 + mt * 16 + gid;
        const float b0 = pbias[r0], b1 = pbias[r0 + 8];
#pragma unroll
        for (int nt = 0; nt < 8; nt++) {
            const int col = n0 + wn * 64 + nt * 8 + 2 * tid4;
            *(float2*)(yb + (size_t)r0 * NVOX + col) =
                make_float2(acc[mt][nt][0] + b0, acc[mt][nt][1] + b0);
            *(float2*)(yb + (size_t)(r0 + 8) * NVOX + col) =
                make_float2(acc[mt][nt][2] + b1, acc[mt][nt][3] + b1);
        }
    }
}

// ---------------------------------------------------------------------------
extern "C" void kernel_launch(void* const* d_in, const int* in_sizes, int n_in,
                              void* d_out, int out_size)
{
    const float* x      = (const float*)d_in[0];
    const float* qkv_w  = (const float*)d_in[1];
    const float* qkv_b  = (const float*)d_in[2];
    const float* temp   = (const float*)d_in[3];
    const float* proj_w = (const float*)d_in[4];
    const float* proj_b = (const float*)d_in[5];
    float* y = (float*)d_out;

    gw_kernel     <<<dim3(6, 6), 256>>>(qkv_w);
    wb_kernel     <<<1, 256>>>(qkv_w, qkv_b);
    z_gemm        <<<dim3(NVOX / 128, 1, BATCH), 256>>>(x);
    v_gemm        <<<dim3(48, 3, BATCH), 256>>>(x, qkv_w, qkv_b);
    scores_kernel <<<dim3(6, HEADS, BATCH), 256>>>(x);
    softmax_kernel<<<dim3(HEADS, BATCH), 256>>>(temp);
    mmix_kernel   <<<dim3(HEADS, BATCH), 192>>>(proj_w);
    out_gemm      <<<dim3(NVOX / 128, 1, BATCH), 256>>>(y, proj_b);
}

// round 4
// speedup vs baseline: 2.2204x; 1.0077x over previous
#include <cuda_runtime.h>
#include <math.h>

#define BATCH  8
#define CH     192
#define C3     576
#define NVOX   13824       // 24*24*24
#define HEADS  6
#define HD     32
#define EPSN   1e-12f

// Scratch
__device__ float g_Z[(size_t)BATCH * CH * NVOX];     // Z = Gw @ X   (85 MB)
__device__ float g_V[(size_t)BATCH * NVOX * CH];     // Vbuf         (85 MB)
__device__ float g_Gw[CH * CH];
__device__ float g_wb[CH];
__device__ float g_pwT[CH * CH];                     // proj_w transposed
__device__ float g_c[4];                             // [0] = b2
__device__ float g_spart[BATCH * HEADS * 6 * 1152];  // S1(1024)+d1q+d1k+wbq+wbk
__device__ float g_attn[BATCH * HEADS * HD * HD];
__device__ float g_M[BATCH * CH * CH];

// ---------------------------------------------------------------------------
__device__ __forceinline__ unsigned f2tf(float f) {
    unsigned u;
    asm("cvt.rna.tf32.f32 %0, %1;" : "=r"(u) : "f"(f));
    return u;
}
__device__ __forceinline__ void mma_tf32(float* c, const unsigned* a, const unsigned* b) {
    asm volatile(
        "mma.sync.aligned.m16n8k8.row.col.f32.tf32.tf32.f32 "
        "{%0,%1,%2,%3},{%4,%5,%6,%7},{%8,%9},{%0,%1,%2,%3};"
        : "+f"(c[0]), "+f"(c[1]), "+f"(c[2]), "+f"(c[3])
        : "r"(a[0]), "r"(a[1]), "r"(a[2]), "r"(a[3]), "r"(b[0]), "r"(b[1]));
}

// ---------------------------------------------------------------------------
// K0a: Gw = W^T W  (192x192, fp32). grid(6,6), 256 thr.
// ---------------------------------------------------------------------------
__global__ __launch_bounds__(256) void gw_kernel(const float* __restrict__ w)
{
    __shared__ float Wi[32][33];
    __shared__ float Wj[32][33];
    const int i0 = blockIdx.x * 32, j0 = blockIdx.y * 32;
    const int t = threadIdx.x;
    const int ti = t & 31, tj = (t >> 5) * 4;
    float acc[4] = {0.f, 0.f, 0.f, 0.f};

    for (int a0 = 0; a0 < C3; a0 += 32) {
        __syncthreads();
#pragma unroll
        for (int l = 0; l < 4; l++) {
            const int a = (t >> 5) + 8 * l, c = t & 31;
            Wi[a][c] = w[(a0 + a) * CH + i0 + c];
            Wj[a][c] = w[(a0 + a) * CH + j0 + c];
        }
        __syncthreads();
#pragma unroll
        for (int a = 0; a < 32; a++) {
            const float wi = Wi[a][ti];
#pragma unroll
            for (int r = 0; r < 4; r++) acc[r] += wi * Wj[a][tj + r];
        }
    }
#pragma unroll
    for (int r = 0; r < 4; r++) g_Gw[(i0 + ti) * CH + j0 + tj + r] = acc[r];
}

// K0b: wb = W^T beta; b2 = sum beta^2.
__global__ __launch_bounds__(256) void wb_kernel(const float* __restrict__ w,
                                                 const float* __restrict__ beta)
{
    __shared__ float red[64];
    const int t = threadIdx.x;
    if (t < CH) {
        float s = 0.f;
        for (int a = 0; a < C3; a++) s += beta[a] * w[a * CH + t];
        g_wb[t] = s;
    }
    if (t < 64) {
        float p = 0.f;
        for (int a = t; a < C3; a += 64) p += beta[a] * beta[a];
        red[t] = p;
    }
    __syncthreads();
    if (t == 0) {
        float s = 0.f;
        for (int i = 0; i < 64; i++) s += red[i];
        g_c[0] = s;
    }
}

// K0c: pwT[c][o] = proj_w[o][c]
__global__ __launch_bounds__(256) void ptrans_kernel(const float* __restrict__ pw)
{
    __shared__ float tile[32][33];
    const int bx = blockIdx.x * 32, by = blockIdx.y * 32;
    const int tx = threadIdx.x & 31, ty = threadIdx.x >> 5;
#pragma unroll
    for (int l = 0; l < 4; l++)
        tile[ty + 8 * l][tx] = pw[(by + ty + 8 * l) * CH + bx + tx];
    __syncthreads();
#pragma unroll
    for (int l = 0; l < 4; l++)
        g_pwT[(bx + ty + 8 * l) * CH + by + tx] = tile[tx][ty + 8 * l];
}

// ---------------------------------------------------------------------------
// K1: Z[b] = Gw(192x192) @ X[b](192x13824).  BM=192, BN=128, BK=16.
// 512 thr, 16 warps 4m x 4n, warp tile 48x32 (3x4 m16n8k8).
// ---------------------------------------------------------------------------
__global__ __launch_bounds__(512, 1) void z_gemm(const float* __restrict__ x)
{
    __shared__ unsigned As[192 * 20];
    __shared__ unsigned Bs[16 * 136];

    const int b  = blockIdx.z;
    const int n0 = blockIdx.x * 128;
    const int t  = threadIdx.x;
    const int wid = t >> 5, lane = t & 31;
    const int wm = wid >> 2, wn = wid & 3;
    const int gid = lane >> 2, tid4 = lane & 3;

    const float* xb = x + (size_t)b * CH * NVOX;
    float* zb = g_Z + (size_t)b * CH * NVOX;

    float acc[3][4][4];
#pragma unroll
    for (int i = 0; i < 3; i++)
#pragma unroll
        for (int j = 0; j < 4; j++)
#pragma unroll
            for (int e = 0; e < 4; e++) acc[i][j][e] = 0.f;

    const int arow0 = t >> 2, akq = (t & 3) * 4;
    const int arow1 = 128 + (t >> 2);
    const int bkr = t >> 5, bnq = t & 31;

    float4 ar0, ar1, br;
    ar0 = *(const float4*)(g_Gw + arow0 * CH + akq);
    if (t < 256) ar1 = *(const float4*)(g_Gw + arow1 * CH + akq);
    br = *(const float4*)(xb + (size_t)bkr * NVOX + n0 + bnq * 4);

    for (int k0 = 0; k0 < CH; k0 += 16) {
        __syncthreads();
        {
            unsigned* d = &As[arow0 * 20 + akq];
            d[0] = f2tf(ar0.x); d[1] = f2tf(ar0.y); d[2] = f2tf(ar0.z); d[3] = f2tf(ar0.w);
        }
        if (t < 256) {
            unsigned* d = &As[arow1 * 20 + akq];
            d[0] = f2tf(ar1.x); d[1] = f2tf(ar1.y); d[2] = f2tf(ar1.z); d[3] = f2tf(ar1.w);
        }
        {
            unsigned* d = &Bs[bkr * 136 + bnq * 4];
            d[0] = f2tf(br.x); d[1] = f2tf(br.y); d[2] = f2tf(br.z); d[3] = f2tf(br.w);
        }
        __syncthreads();
        if (k0 + 16 < CH) {
            ar0 = *(const float4*)(g_Gw + arow0 * CH + k0 + 16 + akq);
            if (t < 256) ar1 = *(const float4*)(g_Gw + arow1 * CH + k0 + 16 + akq);
            br = *(const float4*)(xb + (size_t)(k0 + 16 + bkr) * NVOX + n0 + bnq * 4);
        }
#pragma unroll
        for (int kk = 0; kk < 16; kk += 8) {
            unsigned af[3][4], bf[4][2];
#pragma unroll
            for (int mt = 0; mt < 3; mt++) {
                const int row = wm * 48 + mt * 16 + gid;
                af[mt][0] = As[row * 20 + kk + tid4];
                af[mt][1] = As[(row + 8) * 20 + kk + tid4];
                af[mt][2] = As[row * 20 + kk + tid4 + 4];
                af[mt][3] = As[(row + 8) * 20 + kk + tid4 + 4];
            }
#pragma unroll
            for (int nt = 0; nt < 4; nt++) {
                const int col = wn * 32 + nt * 8 + gid;
                bf[nt][0] = Bs[(kk + tid4) * 136 + col];
                bf[nt][1] = Bs[(kk + tid4 + 4) * 136 + col];
            }
#pragma unroll
            for (int mt = 0; mt < 3; mt++)
#pragma unroll
                for (int nt = 0; nt < 4; nt++)
                    mma_tf32(acc[mt][nt], af[mt], bf[nt]);
        }
    }

#pragma unroll
    for (int mt = 0; mt < 3; mt++) {
        const int r0 = wm * 48 + mt * 16 + gid;
#pragma unroll
        for (int nt = 0; nt < 4; nt++) {
            const int col = n0 + wn * 32 + nt * 8 + 2 * tid4;
            *(float2*)(zb + (size_t)r0 * NVOX + col) = make_float2(acc[mt][nt][0], acc[mt][nt][1]);
            *(float2*)(zb + (size_t)(r0 + 8) * NVOX + col) = make_float2(acc[mt][nt][2], acc[mt][nt][3]);
        }
    }
}

// ---------------------------------------------------------------------------
// K2: Vbuf GEMM. BM=192 (w-rows m0..), BN=96 (p cols). 512 thr, 16 warps
// 4m x 4n, warp tile 48x24 (3x3 tiles).
// ---------------------------------------------------------------------------
__global__ __launch_bounds__(512, 1) void v_gemm(const float* __restrict__ x,
                                                 const float* __restrict__ w,
                                                 const float* __restrict__ beta)
{
    __shared__ unsigned As[192 * 20];
    __shared__ unsigned Bs[16 * 104];

    const int b  = blockIdx.z;
    const int m0 = blockIdx.y * 192;
    const int p0 = blockIdx.x * 96;
    const int e  = p0 / 192;
    const int j0 = p0 % 192;
    const int t  = threadIdx.x;
    const int wid = t >> 5, lane = t & 31;
    const int wm = wid >> 2, wn = wid & 3;
    const int gid = lane >> 2, tid4 = lane & 3;

    const float* xb = x + (size_t)b * CH * NVOX + 576 * e + 384 + j0;
    float* vb = g_V + (size_t)b * NVOX * CH;

    float acc[3][3][4];
#pragma unroll
    for (int i = 0; i < 3; i++)
#pragma unroll
        for (int j = 0; j < 3; j++)
#pragma unroll
            for (int q = 0; q < 4; q++) acc[i][j][q] = 0.f;

    const int arow0 = t >> 2, akq = (t & 3) * 4;
    const int arow1 = 128 + (t >> 2);
    const int bkr = t / 24, bc = t % 24;     // valid for t<384

    float4 ar0, ar1, br;
    ar0 = *(const float4*)(w + (size_t)(m0 + arow0) * CH + akq);
    if (t < 256) ar1 = *(const float4*)(w + (size_t)(m0 + arow1) * CH + akq);
    if (t < 384) br = *(const float4*)(xb + (size_t)bkr * NVOX + bc * 4);

    for (int k0 = 0; k0 < CH; k0 += 16) {
        __syncthreads();
        {
            unsigned* d = &As[arow0 * 20 + akq];
            d[0] = f2tf(ar0.x); d[1] = f2tf(ar0.y); d[2] = f2tf(ar0.z); d[3] = f2tf(ar0.w);
        }
        if (t < 256) {
            unsigned* d = &As[arow1 * 20 + akq];
            d[0] = f2tf(ar1.x); d[1] = f2tf(ar1.y); d[2] = f2tf(ar1.z); d[3] = f2tf(ar1.w);
        }
        if (t < 384) {
            unsigned* d = &Bs[bkr * 104 + bc * 4];
            d[0] = f2tf(br.x); d[1] = f2tf(br.y); d[2] = f2tf(br.z); d[3] = f2tf(br.w);
        }
        __syncthreads();
        if (k0 + 16 < CH) {
            ar0 = *(const float4*)(w + (size_t)(m0 + arow0) * CH + k0 + 16 + akq);
            if (t < 256) ar1 = *(const float4*)(w + (size_t)(m0 + arow1) * CH + k0 + 16 + akq);
            if (t < 384) br = *(const float4*)(xb + (size_t)(k0 + 16 + bkr) * NVOX + bc * 4);
        }
#pragma unroll
        for (int kk = 0; kk < 16; kk += 8) {
            unsigned af[3][4], bf[3][2];
#pragma unroll
            for (int mt = 0; mt < 3; mt++) {
                const int row = wm * 48 + mt * 16 + gid;
                af[mt][0] = As[row * 20 + kk + tid4];
                af[mt][1] = As[(row + 8) * 20 + kk + tid4];
                af[mt][2] = As[row * 20 + kk + tid4 + 4];
                af[mt][3] = As[(row + 8) * 20 + kk + tid4 + 4];
            }
#pragma unroll
            for (int nt = 0; nt < 3; nt++) {
                const int col = wn * 24 + nt * 8 + gid;
                bf[nt][0] = Bs[(kk + tid4) * 104 + col];
                bf[nt][1] = Bs[(kk + tid4 + 4) * 104 + col];
            }
#pragma unroll
            for (int mt = 0; mt < 3; mt++)
#pragma unroll
                for (int nt = 0; nt < 3; nt++)
                    mma_tf32(acc[mt][nt], af[mt], bf[nt]);
        }
    }

#pragma unroll
    for (int mt = 0; mt < 3; mt++) {
        const int r0 = m0 + wm * 48 + mt * 16 + gid;
        const float b0 = beta[r0], b1 = beta[r0 + 8];
#pragma unroll
        for (int nt = 0; nt < 3; nt++) {
            const int pc = p0 + wn * 24 + nt * 8 + 2 * tid4;
            *(float2*)(vb + (size_t)r0 * 4608 + pc) =
                make_float2(acc[mt][nt][0] + b0, acc[mt][nt][1] + b0);
            *(float2*)(vb + (size_t)(r0 + 8) * 4608 + pc) =
                make_float2(acc[mt][nt][2] + b1, acc[mt][nt][3] + b1);
        }
    }
}

// ---------------------------------------------------------------------------
// K3: score partials, float4 loads, double-buffered e-loop.
// ---------------------------------------------------------------------------
__global__ __launch_bounds__(256) void scores_kernel(const float* __restrict__ x)
{
    __shared__ float Xq[2][32][36], Zq[2][32][36], Xk[2][32][36], Zk[2][32][36];
    __shared__ float wbs[32];

    const int isl = blockIdx.x, h = blockIdx.y, b = blockIdx.z;
    const int i0  = isl * 32;
    const int t   = threadIdx.x;
    const int h32 = h * 32;

    const float* xb = x + (size_t)b * CH * NVOX;
    const float* zb = g_Z + (size_t)b * CH * NVOX;

    if (t < 32) wbs[t] = g_wb[i0 + t];

    const int li  = t >> 3;          // row (channel within slice) 0..31
    const int lc4 = (t & 7) << 2;    // col quad 0,4,...,28
    const int cc  = t >> 3;
    const int d0  = (t & 7) << 2;

    float s[4] = {0.f, 0.f, 0.f, 0.f};
    float dac = 0.f, wac = 0.f;

    const size_t rowoff = (size_t)(i0 + li) * NVOX;
    float4 rq, rzq, rk, rzk;
    {
        const int u = h32 + lc4;
        rq  = *(const float4*)(xb + rowoff + u);
        rzq = *(const float4*)(zb + rowoff + u);
        rk  = *(const float4*)(xb + rowoff + u + 192);
        rzk = *(const float4*)(zb + rowoff + u + 192);
    }
    *(float4*)&Xq[0][li][lc4] = rq;  *(float4*)&Zq[0][li][lc4] = rzq;
    *(float4*)&Xk[0][li][lc4] = rk;  *(float4*)&Zk[0][li][lc4] = rzk;
    __syncthreads();

    for (int e = 0; e < 24; e++) {
        const int cur = e & 1, nxt = cur ^ 1;
        if (e < 23) {
            const int u = 576 * (e + 1) + h32 + lc4;
            rq  = *(const float4*)(xb + rowoff + u);
            rzq = *(const float4*)(zb + rowoff + u);
            rk  = *(const float4*)(xb + rowoff + u + 192);
            rzk = *(const float4*)(zb + rowoff + u + 192);
        }
#pragma unroll
        for (int i = 0; i < 32; i++) {
            const float qv = Xq[cur][i][cc];
            const float4 zv = *(const float4*)&Zk[cur][i][d0];
            s[0] += qv * zv.x; s[1] += qv * zv.y; s[2] += qv * zv.z; s[3] += qv * zv.w;
        }
        if (t < 32) {
#pragma unroll
            for (int i = 0; i < 32; i++) {
                const float xv = Xq[cur][i][t];
                dac += xv * Zq[cur][i][t];
                wac += wbs[i] * xv;
            }
        } else if (t < 64) {
            const int c = t - 32;
#pragma unroll
            for (int i = 0; i < 32; i++) {
                const float xv = Xk[cur][i][c];
                dac += xv * Zk[cur][i][c];
                wac += wbs[i] * xv;
            }
        }
        if (e < 23) {
            *(float4*)&Xq[nxt][li][lc4] = rq;  *(float4*)&Zq[nxt][li][lc4] = rzq;
            *(float4*)&Xk[nxt][li][lc4] = rk;  *(float4*)&Zk[nxt][li][lc4] = rzk;
        }
        __syncthreads();
    }

    float* sp = g_spart + (size_t)((b * HEADS + h) * 6 + isl) * 1152;
    sp[cc * 32 + d0 + 0] = s[0];
    sp[cc * 32 + d0 + 1] = s[1];
    sp[cc * 32 + d0 + 2] = s[2];
    sp[cc * 32 + d0 + 3] = s[3];
    if (t < 32)       { sp[1024 + t] = dac; sp[1088 + t] = wac; }
    else if (t < 64)  { sp[1056 + (t - 32)] = dac; sp[1120 + (t - 32)] = wac; }
}

// ---------------------------------------------------------------------------
// K4: reduce partials, assemble S + bias terms, normalize, softmax -> attn
// ---------------------------------------------------------------------------
__global__ __launch_bounds__(256) void softmax_kernel(const float* __restrict__ temp)
{
    __shared__ float sS[1024];
    __shared__ float snq[32], snk[32], swq[32], swk[32];

    const int h = blockIdx.x, b = blockIdx.y;
    const int t = threadIdx.x;
    const float b2 = g_c[0];
    const float* sp = g_spart + (size_t)((b * HEADS + h) * 6) * 1152;

#pragma unroll
    for (int i = 0; i < 4; i++) {
        const int e = t + i * 256;
        float a = 0.f;
        for (int s = 0; s < 6; s++) a += sp[s * 1152 + e];
        sS[e] = a;
    }
    if (t < 64) {
        float d = 0.f, wv = 0.f;
        const int od = 1024 + t, ow = 1088 + t;
        for (int s = 0; s < 6; s++) { d += sp[s * 1152 + od]; wv += sp[s * 1152 + ow]; }
        const float n2 = d + 2.f * wv + 24.f * b2;
        const float r = fmaxf(sqrtf(fmaxf(n2, 0.f)), EPSN);
        if (t < 32) { snq[t] = r; swq[t] = wv; }
        else        { snk[t - 32] = r; swk[t - 32] = wv; }
    }
    __syncthreads();

    const int w = t >> 5, lane = t & 31;
    const float tv = temp[h];
    float* ab = g_attn + (size_t)((b * HEADS + h) * HD) * HD;

    for (int r = 0; r < 4; r++) {
        const int c = w * 4 + r;
        const float Sfull = sS[c * 32 + lane] + swq[c] + swk[lane] + 24.f * b2;
        float L = Sfull / (snq[c] * snk[lane]) * tv;
        float mx = L;
#pragma unroll
        for (int o = 16; o > 0; o >>= 1) mx = fmaxf(mx, __shfl_xor_sync(0xffffffffu, mx, o));
        const float ev = expf(L - mx);
        float sm = ev;
#pragma unroll
        for (int o = 16; o > 0; o >>= 1) sm += __shfl_xor_sync(0xffffffffu, sm, o);
        ab[c * 32 + lane] = ev / sm;
    }
}

// ---------------------------------------------------------------------------
// K5: M[b][o][h*32+d] = sum_cc pwT[cc*6+h][o] * attn[b,h,cc,d]  (coalesced)
// ---------------------------------------------------------------------------
__global__ __launch_bounds__(192) void mmix_kernel()
{
    __shared__ float att[32][33];
    const int h = blockIdx.x, b = blockIdx.y;
    const int t = threadIdx.x;

    const float* ab = g_attn + (size_t)((b * HEADS + h) * HD) * HD;
    for (int e = t; e < 1024; e += 192) att[e >> 5][e & 31] = ab[e];
    __syncthreads();

    float pwr[32];
#pragma unroll
    for (int cc = 0; cc < 32; cc++) pwr[cc] = g_pwT[(cc * HEADS + h) * CH + t];

    float* Mb = g_M + (size_t)b * CH * CH + t * CH + h * HD;
#pragma unroll 4
    for (int d = 0; d < 32; d++) {
        float s = 0.f;
#pragma unroll
        for (int cc = 0; cc < 32; cc++) s += pwr[cc] * att[cc][d];
        Mb[d] = s;
    }
}

// ---------------------------------------------------------------------------
// K6: y[b] = M[b](192x192) @ Vbuf[b]^T + proj_b.  BM=192, BN=128, 512 thr,
// 16 warps 4m x 4n, warp tile 48x32.
// ---------------------------------------------------------------------------
__global__ __launch_bounds__(512, 1) void out_gemm(float* __restrict__ y,
                                                   const float* __restrict__ pbias)
{
    __shared__ unsigned As[192 * 20];
    __shared__ unsigned Bs[128 * 20];

    const int b  = blockIdx.z;
    const int n0 = blockIdx.x * 128;
    const int t  = threadIdx.x;
    const int wid = t >> 5, lane = t & 31;
    const int wm = wid >> 2, wn = wid & 3;
    const int gid = lane >> 2, tid4 = lane & 3;

    const float* Mb = g_M + (size_t)b * CH * CH;
    const float* vb = g_V + (size_t)b * NVOX * CH;
    float* yb = y + (size_t)b * CH * NVOX;

    float acc[3][4][4];
#pragma unroll
    for (int i = 0; i < 3; i++)
#pragma unroll
        for (int j = 0; j < 4; j++)
#pragma unroll
            for (int e = 0; e < 4; e++) acc[i][j][e] = 0.f;

    const int arow0 = t >> 2, akq = (t & 3) * 4;
    const int arow1 = 128 + (t >> 2);
    const int bn = t >> 2, bkq = (t & 3) * 4;

    float4 ar0, ar1, br;
    ar0 = *(const float4*)(Mb + arow0 * CH + akq);
    if (t < 256) ar1 = *(const float4*)(Mb + arow1 * CH + akq);
    br = *(const float4*)(vb + (size_t)(n0 + bn) * CH + bkq);

    for (int k0 = 0; k0 < CH; k0 += 16) {
        __syncthreads();
        {
            unsigned* d = &As[arow0 * 20 + akq];
            d[0] = f2tf(ar0.x); d[1] = f2tf(ar0.y); d[2] = f2tf(ar0.z); d[3] = f2tf(ar0.w);
        }
        if (t < 256) {
            unsigned* d = &As[arow1 * 20 + akq];
            d[0] = f2tf(ar1.x); d[1] = f2tf(ar1.y); d[2] = f2tf(ar1.z); d[3] = f2tf(ar1.w);
        }
        {
            unsigned* d = &Bs[bn * 20 + bkq];
            d[0] = f2tf(br.x); d[1] = f2tf(br.y); d[2] = f2tf(br.z); d[3] = f2tf(br.w);
        }
        __syncthreads();
        if (k0 + 16 < CH) {
            ar0 = *(const float4*)(Mb + arow0 * CH + k0 + 16 + akq);
            if (t < 256) ar1 = *(const float4*)(Mb + arow1 * CH + k0 + 16 + akq);
            br = *(const float4*)(vb + (size_t)(n0 + bn) * CH + k0 + 16 + bkq);
        }
#pragma unroll
        for (int kk = 0; kk < 16; kk += 8) {
            unsigned af[3][4], bf[4][2];
#pragma unroll
            for (int mt = 0; mt < 3; mt++) {
                const int row = wm * 48 + mt * 16 + gid;
                af[mt][0] = As[row * 20 + kk + tid4];
                af[mt][1] = As[(row + 8) * 20 + kk + tid4];
                af[mt][2] = As[row * 20 + kk + tid4 + 4];
                af[mt][3] = As[(row + 8) * 20 + kk + tid4 + 4];
            }
#pragma unroll
            for (int nt = 0; nt < 4; nt++) {
                const int col = wn * 32 + nt * 8 + gid;
                bf[nt][0] = Bs[col * 20 + kk + tid4];
                bf[nt][1] = Bs[col * 20 + kk + tid4 + 4];
            }
#pragma unroll
            for (int mt = 0; mt < 3; mt++)
#pragma unroll
                for (int nt = 0; nt < 4; nt++)
                    mma_tf32(acc[mt][nt], af[mt], bf[nt]);
        }
    }

#pragma unroll
    for (int mt = 0; mt < 3; mt++) {
        const int r0 = wm * 48 + mt * 16 + gid;
        const float b0 = pbias[r0], b1 = pbias[r0 + 8];
#pragma unroll
        for (int nt = 0; nt < 4; nt++) {
            const int col = n0 + wn * 32 + nt * 8 + 2 * tid4;
            *(float2*)(yb + (size_t)r0 * NVOX + col) =
                make_float2(acc[mt][nt][0] + b0, acc[mt][nt][1] + b0);
            *(float2*)(yb + (size_t)(r0 + 8) * NVOX + col) =
                make_float2(acc[mt][nt][2] + b1, acc[mt][nt][3] + b1);
        }
    }
}

// ---------------------------------------------------------------------------
extern "C" void kernel_launch(void* const* d_in, const int* in_sizes, int n_in,
                              void* d_out, int out_size)
{
    const float* x      = (const float*)d_in[0];
    const float* qkv_w  = (const float*)d_in[1];
    const float* qkv_b  = (const float*)d_in[2];
    const float* temp   = (const float*)d_in[3];
    const float* proj_w = (const float*)d_in[4];
    const float* proj_b = (const float*)d_in[5];
    float* y = (float*)d_out;

    gw_kernel     <<<dim3(6, 6), 256>>>(qkv_w);
    wb_kernel     <<<1, 256>>>(qkv_w, qkv_b);
    ptrans_kernel <<<dim3(6, 6), 256>>>(proj_w);
    z_gemm        <<<dim3(NVOX / 128, 1, BATCH), 512>>>(x);
    v_gemm        <<<dim3(48, 3, BATCH), 512>>>(x, qkv_w, qkv_b);
    scores_kernel <<<dim3(6, HEADS, BATCH), 256>>>(x);
    softmax_kernel<<<dim3(HEADS, BATCH), 256>>>(temp);
    mmix_kernel   <<<dim3(HEADS, BATCH), 192>>>();
    out_gemm      <<<dim3(NVOX / 128, 1, BATCH), 512>>>(y, proj_b);
}

// round 5
// speedup vs baseline: 2.7973x; 1.2598x over previous
#include <cuda_runtime.h>
#include <math.h>

#define BATCH  8
#define CH     192
#define C3     576
#define NVOX   13824       // 24*24*24
#define HEADS  6
#define HD     32
#define EPSN   1e-12f

// Scratch
__device__ float g_Z[(size_t)BATCH * CH * NVOX];     // Z = Gw @ X (only q/k cols valid)
__device__ float g_V[(size_t)BATCH * NVOX * CH];     // Vbuf
__device__ float g_Gw[CH * CH];
__device__ float g_wb[CH];
__device__ float g_pwT[CH * CH];
__device__ float g_c[4];                             // [0] = b2
__device__ float g_spart[BATCH * HEADS * 6 * 1152];  // S1(1024)+d1q+d1k+wbq+wbk
__device__ float g_attn[BATCH * HEADS * HD * HD];
__device__ float g_M[BATCH * CH * CH];

// ---------------------------------------------------------------------------
__device__ __forceinline__ unsigned f2tf(float f) {
    unsigned u;
    asm("cvt.rna.tf32.f32 %0, %1;" : "=r"(u) : "f"(f));
    return u;
}
__device__ __forceinline__ void mma_tf32(float* c, const unsigned* a, const unsigned* b) {
    asm volatile(
        "mma.sync.aligned.m16n8k8.row.col.f32.tf32.tf32.f32 "
        "{%0,%1,%2,%3},{%4,%5,%6,%7},{%8,%9},{%0,%1,%2,%3};"
        : "+f"(c[0]), "+f"(c[1]), "+f"(c[2]), "+f"(c[3])
        : "r"(a[0]), "r"(a[1]), "r"(a[2]), "r"(a[3]), "r"(b[0]), "r"(b[1]));
}

// ---------------------------------------------------------------------------
// K0a: Gw = W^T W
// ---------------------------------------------------------------------------
__global__ __launch_bounds__(256) void gw_kernel(const float* __restrict__ w)
{
    __shared__ float Wi[32][33];
    __shared__ float Wj[32][33];
    const int i0 = blockIdx.x * 32, j0 = blockIdx.y * 32;
    const int t = threadIdx.x;
    const int ti = t & 31, tj = (t >> 5) * 4;
    float acc[4] = {0.f, 0.f, 0.f, 0.f};

    for (int a0 = 0; a0 < C3; a0 += 32) {
        __syncthreads();
#pragma unroll
        for (int l = 0; l < 4; l++) {
            const int a = (t >> 5) + 8 * l, c = t & 31;
            Wi[a][c] = w[(a0 + a) * CH + i0 + c];
            Wj[a][c] = w[(a0 + a) * CH + j0 + c];
        }
        __syncthreads();
#pragma unroll
        for (int a = 0; a < 32; a++) {
            const float wi = Wi[a][ti];
#pragma unroll
            for (int r = 0; r < 4; r++) acc[r] += wi * Wj[a][tj + r];
        }
    }
#pragma unroll
    for (int r = 0; r < 4; r++) g_Gw[(i0 + ti) * CH + j0 + tj + r] = acc[r];
}

// K0b: wb = W^T beta; b2 = sum beta^2.
__global__ __launch_bounds__(256) void wb_kernel(const float* __restrict__ w,
                                                 const float* __restrict__ beta)
{
    __shared__ float red[64];
    const int t = threadIdx.x;
    if (t < CH) {
        float s = 0.f;
        for (int a = 0; a < C3; a++) s += beta[a] * w[a * CH + t];
        g_wb[t] = s;
    }
    if (t < 64) {
        float p = 0.f;
        for (int a = t; a < C3; a += 64) p += beta[a] * beta[a];
        red[t] = p;
    }
    __syncthreads();
    if (t == 0) {
        float s = 0.f;
        for (int i = 0; i < 64; i++) s += red[i];
        g_c[0] = s;
    }
}

// K0c: pwT[c][o] = proj_w[o][c]
__global__ __launch_bounds__(256) void ptrans_kernel(const float* __restrict__ pw)
{
    __shared__ float tile[32][33];
    const int bx = blockIdx.x * 32, by = blockIdx.y * 32;
    const int tx = threadIdx.x & 31, ty = threadIdx.x >> 5;
#pragma unroll
    for (int l = 0; l < 4; l++)
        tile[ty + 8 * l][tx] = pw[(by + ty + 8 * l) * CH + bx + tx];
    __syncthreads();
#pragma unroll
    for (int l = 0; l < 4; l++)
        g_pwT[(bx + ty + 8 * l) * CH + by + tx] = tile[tx][ty + 8 * l];
}

// ---------------------------------------------------------------------------
// K1: Z[b] = Gw @ X[b], ONLY columns 576e + [0,384).
// BM=192, BN=192, BK=16, 384 thr, 12 warps (4m x 3n), warp 48x64 (3x8).
// ---------------------------------------------------------------------------
__global__ __launch_bounds__(384, 1) void z_gemm(const float* __restrict__ x)
{
    __shared__ unsigned As[192 * 20];
    __shared__ unsigned Bs[16 * 200];

    const int b  = blockIdx.z;
    const int n0 = 576 * (blockIdx.x >> 1) + 192 * (blockIdx.x & 1);
    const int t  = threadIdx.x;
    const int wid = t >> 5, lane = t & 31;
    const int wm = wid & 3, wn = wid >> 2;     // wm 0..3, wn 0..2
    const int gid = lane >> 2, tid4 = lane & 3;

    const float* xb = x + (size_t)b * CH * NVOX;
    float* zb = g_Z + (size_t)b * CH * NVOX;

    float acc[3][8][4];
#pragma unroll
    for (int i = 0; i < 3; i++)
#pragma unroll
        for (int j = 0; j < 8; j++)
#pragma unroll
            for (int e = 0; e < 4; e++) acc[i][j][e] = 0.f;

    float4 ar[2], br[2];
#pragma unroll
    for (int l = 0; l < 2; l++) {
        const int idx = l * 384 + t;
        ar[l] = *(const float4*)(g_Gw + (idx >> 2) * CH + (idx & 3) * 4);
        br[l] = *(const float4*)(xb + (size_t)(idx / 48) * NVOX + n0 + (idx % 48) * 4);
    }

    for (int k0 = 0; k0 < CH; k0 += 16) {
        __syncthreads();
#pragma unroll
        for (int l = 0; l < 2; l++) {
            const int idx = l * 384 + t;
            unsigned* da = &As[(idx >> 2) * 20 + (idx & 3) * 4];
            da[0] = f2tf(ar[l].x); da[1] = f2tf(ar[l].y); da[2] = f2tf(ar[l].z); da[3] = f2tf(ar[l].w);
            unsigned* db = &Bs[(idx / 48) * 200 + (idx % 48) * 4];
            db[0] = f2tf(br[l].x); db[1] = f2tf(br[l].y); db[2] = f2tf(br[l].z); db[3] = f2tf(br[l].w);
        }
        __syncthreads();
        if (k0 + 16 < CH) {
#pragma unroll
            for (int l = 0; l < 2; l++) {
                const int idx = l * 384 + t;
                ar[l] = *(const float4*)(g_Gw + (idx >> 2) * CH + k0 + 16 + (idx & 3) * 4);
                br[l] = *(const float4*)(xb + (size_t)(k0 + 16 + idx / 48) * NVOX + n0 + (idx % 48) * 4);
            }
        }
#pragma unroll
        for (int kk = 0; kk < 16; kk += 8) {
            unsigned af[3][4], bf[8][2];
#pragma unroll
            for (int mt = 0; mt < 3; mt++) {
                const int row = wm * 48 + mt * 16 + gid;
                af[mt][0] = As[row * 20 + kk + tid4];
                af[mt][1] = As[(row + 8) * 20 + kk + tid4];
                af[mt][2] = As[row * 20 + kk + tid4 + 4];
                af[mt][3] = As[(row + 8) * 20 + kk + tid4 + 4];
            }
#pragma unroll
            for (int nt = 0; nt < 8; nt++) {
                const int col = wn * 64 + nt * 8 + gid;
                bf[nt][0] = Bs[(kk + tid4) * 200 + col];
                bf[nt][1] = Bs[(kk + tid4 + 4) * 200 + col];
            }
#pragma unroll
            for (int mt = 0; mt < 3; mt++)
#pragma unroll
                for (int nt = 0; nt < 8; nt++)
                    mma_tf32(acc[mt][nt], af[mt], bf[nt]);
        }
    }

#pragma unroll
    for (int mt = 0; mt < 3; mt++) {
        const int r0 = wm * 48 + mt * 16 + gid;
#pragma unroll
        for (int nt = 0; nt < 8; nt++) {
            const int col = n0 + wn * 64 + nt * 8 + 2 * tid4;
            *(float2*)(zb + (size_t)r0 * NVOX + col) = make_float2(acc[mt][nt][0], acc[mt][nt][1]);
            *(float2*)(zb + (size_t)(r0 + 8) * NVOX + col) = make_float2(acc[mt][nt][2], acc[mt][nt][3]);
        }
    }
}

// ---------------------------------------------------------------------------
// K2: Vbuf. A = qkv_w rows [m0, m0+192), B cols 576e+384+[0,192).
// Same tiling as K1. Output vb[a*4608 + e*192 + j] + beta.
// ---------------------------------------------------------------------------
__global__ __launch_bounds__(384, 1) void v_gemm(const float* __restrict__ x,
                                                 const float* __restrict__ w,
                                                 const float* __restrict__ beta)
{
    __shared__ unsigned As[192 * 20];
    __shared__ unsigned Bs[16 * 200];

    const int b  = blockIdx.z;
    const int e  = blockIdx.x;
    const int m0 = blockIdx.y * 192;
    const int t  = threadIdx.x;
    const int wid = t >> 5, lane = t & 31;
    const int wm = wid & 3, wn = wid >> 2;
    const int gid = lane >> 2, tid4 = lane & 3;

    const float* xb = x + (size_t)b * CH * NVOX + 576 * e + 384;
    float* vb = g_V + (size_t)b * NVOX * CH;

    float acc[3][8][4];
#pragma unroll
    for (int i = 0; i < 3; i++)
#pragma unroll
        for (int j = 0; j < 8; j++)
#pragma unroll
            for (int q = 0; q < 4; q++) acc[i][j][q] = 0.f;

    float4 ar[2], br[2];
#pragma unroll
    for (int l = 0; l < 2; l++) {
        const int idx = l * 384 + t;
        ar[l] = *(const float4*)(w + (size_t)(m0 + (idx >> 2)) * CH + (idx & 3) * 4);
        br[l] = *(const float4*)(xb + (size_t)(idx / 48) * NVOX + (idx % 48) * 4);
    }

    for (int k0 = 0; k0 < CH; k0 += 16) {
        __syncthreads();
#pragma unroll
        for (int l = 0; l < 2; l++) {
            const int idx = l * 384 + t;
            unsigned* da = &As[(idx >> 2) * 20 + (idx & 3) * 4];
            da[0] = f2tf(ar[l].x); da[1] = f2tf(ar[l].y); da[2] = f2tf(ar[l].z); da[3] = f2tf(ar[l].w);
            unsigned* db = &Bs[(idx / 48) * 200 + (idx % 48) * 4];
            db[0] = f2tf(br[l].x); db[1] = f2tf(br[l].y); db[2] = f2tf(br[l].z); db[3] = f2tf(br[l].w);
        }
        __syncthreads();
        if (k0 + 16 < CH) {
#pragma unroll
            for (int l = 0; l < 2; l++) {
                const int idx = l * 384 + t;
                ar[l] = *(const float4*)(w + (size_t)(m0 + (idx >> 2)) * CH + k0 + 16 + (idx & 3) * 4);
                br[l] = *(const float4*)(xb + (size_t)(k0 + 16 + idx / 48) * NVOX + (idx % 48) * 4);
            }
        }
#pragma unroll
        for (int kk = 0; kk < 16; kk += 8) {
            unsigned af[3][4], bf[8][2];
#pragma unroll
            for (int mt = 0; mt < 3; mt++) {
                const int row = wm * 48 + mt * 16 + gid;
                af[mt][0] = As[row * 20 + kk + tid4];
                af[mt][1] = As[(row + 8) * 20 + kk + tid4];
                af[mt][2] = As[row * 20 + kk + tid4 + 4];
                af[mt][3] = As[(row + 8) * 20 + kk + tid4 + 4];
            }
#pragma unroll
            for (int nt = 0; nt < 8; nt++) {
                const int col = wn * 64 + nt * 8 + gid;
                bf[nt][0] = Bs[(kk + tid4) * 200 + col];
                bf[nt][1] = Bs[(kk + tid4 + 4) * 200 + col];
            }
#pragma unroll
            for (int mt = 0; mt < 3; mt++)
#pragma unroll
                for (int nt = 0; nt < 8; nt++)
                    mma_tf32(acc[mt][nt], af[mt], bf[nt]);
        }
    }

#pragma unroll
    for (int mt = 0; mt < 3; mt++) {
        const int r0 = m0 + wm * 48 + mt * 16 + gid;
        const float b0 = beta[r0], b1 = beta[r0 + 8];
#pragma unroll
        for (int nt = 0; nt < 8; nt++) {
            const int pc = e * 192 + wn * 64 + nt * 8 + 2 * tid4;
            *(float2*)(vb + (size_t)r0 * 4608 + pc) =
                make_float2(acc[mt][nt][0] + b0, acc[mt][nt][1] + b0);
            *(float2*)(vb + (size_t)(r0 + 8) * 4608 + pc) =
                make_float2(acc[mt][nt][2] + b1, acc[mt][nt][3] + b1);
        }
    }
}

// ---------------------------------------------------------------------------
// K3: score partials, float4 loads, double-buffered e-loop.
// ---------------------------------------------------------------------------
__global__ __launch_bounds__(256) void scores_kernel(const float* __restrict__ x)
{
    __shared__ float Xq[2][32][36], Zq[2][32][36], Xk[2][32][36], Zk[2][32][36];
    __shared__ float wbs[32];

    const int isl = blockIdx.x, h = blockIdx.y, b = blockIdx.z;
    const int i0  = isl * 32;
    const int t   = threadIdx.x;
    const int h32 = h * 32;

    const float* xb = x + (size_t)b * CH * NVOX;
    const float* zb = g_Z + (size_t)b * CH * NVOX;

    if (t < 32) wbs[t] = g_wb[i0 + t];

    const int li  = t >> 3;
    const int lc4 = (t & 7) << 2;
    const int cc  = t >> 3;
    const int d0  = (t & 7) << 2;

    float s[4] = {0.f, 0.f, 0.f, 0.f};
    float dac = 0.f, wac = 0.f;

    const size_t rowoff = (size_t)(i0 + li) * NVOX;
    float4 rq, rzq, rk, rzk;
    {
        const int u = h32 + lc4;
        rq  = *(const float4*)(xb + rowoff + u);
        rzq = *(const float4*)(zb + rowoff + u);
        rk  = *(const float4*)(xb + rowoff + u + 192);
        rzk = *(const float4*)(zb + rowoff + u + 192);
    }
    *(float4*)&Xq[0][li][lc4] = rq;  *(float4*)&Zq[0][li][lc4] = rzq;
    *(float4*)&Xk[0][li][lc4] = rk;  *(float4*)&Zk[0][li][lc4] = rzk;
    __syncthreads();

    for (int e = 0; e < 24; e++) {
        const int cur = e & 1, nxt = cur ^ 1;
        if (e < 23) {
            const int u = 576 * (e + 1) + h32 + lc4;
            rq  = *(const float4*)(xb + rowoff + u);
            rzq = *(const float4*)(zb + rowoff + u);
            rk  = *(const float4*)(xb + rowoff + u + 192);
            rzk = *(const float4*)(zb + rowoff + u + 192);
        }
#pragma unroll
        for (int i = 0; i < 32; i++) {
            const float qv = Xq[cur][i][cc];
            const float4 zv = *(const float4*)&Zk[cur][i][d0];
            s[0] += qv * zv.x; s[1] += qv * zv.y; s[2] += qv * zv.z; s[3] += qv * zv.w;
        }
        if (t < 32) {
#pragma unroll
            for (int i = 0; i < 32; i++) {
                const float xv = Xq[cur][i][t];
                dac += xv * Zq[cur][i][t];
                wac += wbs[i] * xv;
            }
        } else if (t < 64) {
            const int c = t - 32;
#pragma unroll
            for (int i = 0; i < 32; i++) {
                const float xv = Xk[cur][i][c];
                dac += xv * Zk[cur][i][c];
                wac += wbs[i] * xv;
            }
        }
        if (e < 23) {
            *(float4*)&Xq[nxt][li][lc4] = rq;  *(float4*)&Zq[nxt][li][lc4] = rzq;
            *(float4*)&Xk[nxt][li][lc4] = rk;  *(float4*)&Zk[nxt][li][lc4] = rzk;
        }
        __syncthreads();
    }

    float* sp = g_spart + (size_t)((b * HEADS + h) * 6 + isl) * 1152;
    sp[cc * 32 + d0 + 0] = s[0];
    sp[cc * 32 + d0 + 1] = s[1];
    sp[cc * 32 + d0 + 2] = s[2];
    sp[cc * 32 + d0 + 3] = s[3];
    if (t < 32)       { sp[1024 + t] = dac; sp[1088 + t] = wac; }
    else if (t < 64)  { sp[1056 + (t - 32)] = dac; sp[1120 + (t - 32)] = wac; }
}

// ---------------------------------------------------------------------------
// K4: reduce partials, assemble S + bias terms, normalize, softmax -> attn
// ---------------------------------------------------------------------------
__global__ __launch_bounds__(256) void softmax_kernel(const float* __restrict__ temp)
{
    __shared__ float sS[1024];
    __shared__ float snq[32], snk[32], swq[32], swk[32];

    const int h = blockIdx.x, b = blockIdx.y;
    const int t = threadIdx.x;
    const float b2 = g_c[0];
    const float* sp = g_spart + (size_t)((b * HEADS + h) * 6) * 1152;

#pragma unroll
    for (int i = 0; i < 4; i++) {
        const int e = t + i * 256;
        float a = 0.f;
        for (int s = 0; s < 6; s++) a += sp[s * 1152 + e];
        sS[e] = a;
    }
    if (t < 64) {
        float d = 0.f, wv = 0.f;
        const int od = 1024 + t, ow = 1088 + t;
        for (int s = 0; s < 6; s++) { d += sp[s * 1152 + od]; wv += sp[s * 1152 + ow]; }
        const float n2 = d + 2.f * wv + 24.f * b2;
        const float r = fmaxf(sqrtf(fmaxf(n2, 0.f)), EPSN);
        if (t < 32) { snq[t] = r; swq[t] = wv; }
        else        { snk[t - 32] = r; swk[t - 32] = wv; }
    }
    __syncthreads();

    const int w = t >> 5, lane = t & 31;
    const float tv = temp[h];
    float* ab = g_attn + (size_t)((b * HEADS + h) * HD) * HD;

    for (int r = 0; r < 4; r++) {
        const int c = w * 4 + r;
        const float Sfull = sS[c * 32 + lane] + swq[c] + swk[lane] + 24.f * b2;
        float L = Sfull / (snq[c] * snk[lane]) * tv;
        float mx = L;
#pragma unroll
        for (int o = 16; o > 0; o >>= 1) mx = fmaxf(mx, __shfl_xor_sync(0xffffffffu, mx, o));
        const float ev = expf(L - mx);
        float sm = ev;
#pragma unroll
        for (int o = 16; o > 0; o >>= 1) sm += __shfl_xor_sync(0xffffffffu, sm, o);
        ab[c * 32 + lane] = ev / sm;
    }
}

// ---------------------------------------------------------------------------
// K5: M[b][o][h*32+d] = sum_cc pwT[cc*6+h][o] * attn[b,h,cc,d]
// ---------------------------------------------------------------------------
__global__ __launch_bounds__(192) void mmix_kernel()
{
    __shared__ float att[32][33];
    const int h = blockIdx.x, b = blockIdx.y;
    const int t = threadIdx.x;

    const float* ab = g_attn + (size_t)((b * HEADS + h) * HD) * HD;
    for (int e = t; e < 1024; e += 192) att[e >> 5][e & 31] = ab[e];
    __syncthreads();

    float pwr[32];
#pragma unroll
    for (int cc = 0; cc < 32; cc++) pwr[cc] = g_pwT[(cc * HEADS + h) * CH + t];

    float* Mb = g_M + (size_t)b * CH * CH + t * CH + h * HD;
#pragma unroll 4
    for (int d = 0; d < 32; d++) {
        float s = 0.f;
#pragma unroll
        for (int cc = 0; cc < 32; cc++) s += pwr[cc] * att[cc][d];
        Mb[d] = s;
    }
}

// ---------------------------------------------------------------------------
// K6: y[b] = M[b] @ Vbuf[b]^T + proj_b.  BM=192, BN=192, 384 thr, warp 48x64.
// ---------------------------------------------------------------------------
__global__ __launch_bounds__(384, 1) void out_gemm(float* __restrict__ y,
                                                   const float* __restrict__ pbias)
{
    __shared__ unsigned As[192 * 20];
    __shared__ unsigned Bs[192 * 20];

    const int b  = blockIdx.z;
    const int n0 = blockIdx.x * 192;
    const int t  = threadIdx.x;
    const int wid = t >> 5, lane = t & 31;
    const int wm = wid & 3, wn = wid >> 2;
    const int gid = lane >> 2, tid4 = lane & 3;

    const float* Mb = g_M + (size_t)b * CH * CH;
    const float* vb = g_V + (size_t)b * NVOX * CH;
    float* yb = y + (size_t)b * CH * NVOX;

    float acc[3][8][4];
#pragma unroll
    for (int i = 0; i < 3; i++)
#pragma unroll
        for (int j = 0; j < 8; j++)
#pragma unroll
            for (int e = 0; e < 4; e++) acc[i][j][e] = 0.f;

    float4 ar[2], br[2];
#pragma unroll
    for (int l = 0; l < 2; l++) {
        const int idx = l * 384 + t;
        ar[l] = *(const float4*)(Mb + (idx >> 2) * CH + (idx & 3) * 4);
        br[l] = *(const float4*)(vb + (size_t)(n0 + (idx >> 2)) * CH + (idx & 3) * 4);
    }

    for (int k0 = 0; k0 < CH; k0 += 16) {
        __syncthreads();
#pragma unroll
        for (int l = 0; l < 2; l++) {
            const int idx = l * 384 + t;
            unsigned* da = &As[(idx >> 2) * 20 + (idx & 3) * 4];
            da[0] = f2tf(ar[l].x); da[1] = f2tf(ar[l].y); da[2] = f2tf(ar[l].z); da[3] = f2tf(ar[l].w);
            unsigned* db = &Bs[(idx >> 2) * 20 + (idx & 3) * 4];
            db[0] = f2tf(br[l].x); db[1] = f2tf(br[l].y); db[2] = f2tf(br[l].z); db[3] = f2tf(br[l].w);
        }
        __syncthreads();
        if (k0 + 16 < CH) {
#pragma unroll
            for (int l = 0; l < 2; l++) {
                const int idx = l * 384 + t;
                ar[l] = *(const float4*)(Mb + (idx >> 2) * CH + k0 + 16 + (idx & 3) * 4);
                br[l] = *(const float4*)(vb + (size_t)(n0 + (idx >> 2)) * CH + k0 + 16 + (idx & 3) * 4);
            }
        }
#pragma unroll
        for (int kk = 0; kk < 16; kk += 8) {
            unsigned af[3][4], bf[8][2];
#pragma unroll
            for (int mt = 0; mt < 3; mt++) {
                const int row = wm * 48 + mt * 16 + gid;
                af[mt][0] = As[row * 20 + kk + tid4];
                af[mt][1] = As[(row + 8) * 20 + kk + tid4];
                af[mt][2] = As[row * 20 + kk + tid4 + 4];
                af[mt][3] = As[(row + 8) * 20 + kk + tid4 + 4];
            }
#pragma unroll
            for (int nt = 0; nt < 8; nt++) {
                const int col = wn * 64 + nt * 8 + gid;
                bf[nt][0] = Bs[col * 20 + kk + tid4];
                bf[nt][1] = Bs[col * 20 + kk + tid4 + 4];
            }
#pragma unroll
            for (int mt = 0; mt < 3; mt++)
#pragma unroll
                for (int nt = 0; nt < 8; nt++)
                    mma_tf32(acc[mt][nt], af[mt], bf[nt]);
        }
    }

#pragma unroll
    for (int mt = 0; mt < 3; mt++) {
        const int r0 = wm * 48 + mt * 16 + gid;
        const float b0 = pbias[r0], b1 = pbias[r0 + 8];
#pragma unroll
        for (int nt = 0; nt < 8; nt++) {
            const int col = n0 + wn * 64 + nt * 8 + 2 * tid4;
            *(float2*)(yb + (size_t)r0 * NVOX + col) =
                make_float2(acc[mt][nt][0] + b0, acc[mt][nt][1] + b0);
            *(float2*)(yb + (size_t)(r0 + 8) * NVOX + col) =
                make_float2(acc[mt][nt][2] + b1, acc[mt][nt][3] + b1);
        }
    }
}

// ---------------------------------------------------------------------------
extern "C" void kernel_launch(void* const* d_in, const int* in_sizes, int n_in,
                              void* d_out, int out_size)
{
    const float* x      = (const float*)d_in[0];
    const float* qkv_w  = (const float*)d_in[1];
    const float* qkv_b  = (const float*)d_in[2];
    const float* temp   = (const float*)d_in[3];
    const float* proj_w = (const float*)d_in[4];
    const float* proj_b = (const float*)d_in[5];
    float* y = (float*)d_out;

    gw_kernel     <<<dim3(6, 6), 256>>>(qkv_w);
    wb_kernel     <<<1, 256>>>(qkv_w, qkv_b);
    ptrans_kernel <<<dim3(6, 6), 256>>>(proj_w);
    z_gemm        <<<dim3(48, 1, BATCH), 384>>>(x);
    v_gemm        <<<dim3(24, 3, BATCH), 384>>>(x, qkv_w, qkv_b);
    scores_kernel <<<dim3(6, HEADS, BATCH), 256>>>(x);
    softmax_kernel<<<dim3(HEADS, BATCH), 256>>>(temp);
    mmix_kernel   <<<dim3(HEADS, BATCH), 192>>>();
    out_gemm      <<<dim3(72, 1, BATCH), 384>>>(y, proj_b);
}